// round 15
// baseline (speedup 1.0000x reference)
#include <cuda_runtime.h>
#include <cuda_bf16.h>
#include <math.h>
#include <stdint.h>

// Problem dims
#define BATCH   8
#define SEQ     1024
#define DMODEL  1152
#define NHEAD   16
#define HDIM    72
#define SENC    77
#define FFD     4608
#define ROWS    (BATCH*SEQ)        // 8192
#define ENCROWS (BATCH*SENC)       // 616
#define BH      (BATCH*NHEAD)      // 128
#define NROWSBH (BH*SEQ)           // 131072

__device__ __forceinline__ uint32_t smem_to_u32(const void* smem_ptr) {
    uint32_t addr;
    asm("{ .reg .u64 tmp; cvta.to.shared.u64 tmp, %1; cvt.u32.u64 %0, tmp; }"
        : "=r"(addr) : "l"(smem_ptr));
    return addr;
}

// fast exp on the FMA pipe (no MUFU). rel err ~2e-7.
__device__ __forceinline__ float fexp(float x) {
    float t = x * 1.4426950408889634f;
    t = fmaxf(t, -126.0f);
    float fi = floorf(t);
    float f = t - fi;
    float p = 1.3333558146e-3f;
    p = fmaf(p, f, 9.6181291076e-3f);
    p = fmaf(p, f, 5.5504108664e-2f);
    p = fmaf(p, f, 2.4022650695910e-1f);
    p = fmaf(p, f, 6.9314718055994e-1f);
    p = fmaf(p, f, 1.0f);
    return p * __int_as_float(((int)fi + 127) << 23);
}

__device__ __forceinline__ void split_store(
    __nv_bfloat16* __restrict__ h, __nv_bfloat16* __restrict__ l,
    size_t idx, float v)
{
    __nv_bfloat16 hh = __float2bfloat16(v);
    h[idx] = hh;
    l[idx] = __float2bfloat16(v - __bfloat162float(hh));
}

// ----------------------- scratch (device globals; no runtime alloc) ---------
__device__ float g_q[(size_t)ROWS*DMODEL];
__device__ float g_rowZ[NROWSBH];
__device__ float g_partZ[(size_t)NROWSBH*16];
__device__ float g_partM[(size_t)NROWSBH*16];
__device__ float g_proj[(size_t)ROWS*3456];          // fused QKV / KV outputs
__device__ float g_stats[8];
// bf16 hi/lo operand buffers (weight GEMMs)
__device__ __nv_bfloat16 g_ah[(size_t)ROWS*DMODEL];
__device__ __nv_bfloat16 g_al[(size_t)ROWS*DMODEL];
__device__ __nv_bfloat16 g_gh[(size_t)ROWS*FFD];     // geglu output (FF2 A operand)
__device__ __nv_bfloat16 g_gl[(size_t)ROWS*FFD];
__device__ __nv_bfloat16 g_bh[(size_t)(2*FFD)*DMODEL];
__device__ __nv_bfloat16 g_bl[(size_t)(2*FFD)*DMODEL];
// integer-bf16 attention operands
__device__ __nv_bfloat16 g_qi[(size_t)BH*1024*80];
__device__ __nv_bfloat16 g_ki[(size_t)BH*1024*80];
__device__ __nv_bfloat16 g_vi[(size_t)BH*128*1024];

// ----------------------- atomic float min/max -------------------------------
__device__ __forceinline__ void atomicMaxF(float* a, float v) {
    if (v >= 0.f) atomicMax((int*)a, __float_as_int(v));
    else          atomicMin((unsigned int*)a, __float_as_uint(v));
}
__device__ __forceinline__ void atomicMinF(float* a, float v) {
    if (v >= 0.f) atomicMin((int*)a, __float_as_int(v));
    else          atomicMax((unsigned int*)a, __float_as_uint(v));
}

// ----------------------- LayerNorm -> bf16 hi/lo -----------------------------
__global__ __launch_bounds__(256) void ln_split_kernel(
    const float* __restrict__ x, const float* __restrict__ g,
    const float* __restrict__ b,
    __nv_bfloat16* __restrict__ oh, __nv_bfloat16* __restrict__ ol)
{
    const int N = DMODEL;
    size_t row = blockIdx.x;
    const float* xr = x + row * N;
    int tid = threadIdx.x;

    float lv[5];
    int cnt = 0;
    float s = 0.f;
    for (int i = tid; i < N; i += 256) { float t = xr[i]; lv[cnt++] = t; s += t; }

    __shared__ float sh[8];
    for (int ofs = 16; ofs; ofs >>= 1) s += __shfl_xor_sync(0xffffffffu, s, ofs);
    if ((tid & 31) == 0) sh[tid >> 5] = s;
    __syncthreads();
    float tot = 0.f;
    #pragma unroll
    for (int i = 0; i < 8; i++) tot += sh[i];
    float mu = tot * (1.f / (float)N);

    float vs = 0.f;
    for (int c = 0; c < cnt; c++) { float d = lv[c] - mu; vs += d * d; }
    __syncthreads();
    for (int ofs = 16; ofs; ofs >>= 1) vs += __shfl_xor_sync(0xffffffffu, vs, ofs);
    if ((tid & 31) == 0) sh[tid >> 5] = vs;
    __syncthreads();
    float vtot = 0.f;
    #pragma unroll
    for (int i = 0; i < 8; i++) vtot += sh[i];
    float inv = rsqrtf(vtot * (1.f / (float)N) + 1e-5f);

    int i = tid;
    for (int c = 0; c < cnt; c++, i += 256) {
        float val = (lv[c] - mu) * inv * g[i] + b[i];
        split_store(oh, ol, row * N + i, val);
    }
}

// ----------------------- fp32 -> bf16 hi/lo split (for enc) -----------------
__global__ __launch_bounds__(256) void convert_split_kernel(
    const float* __restrict__ x, size_t n4,
    __nv_bfloat16* __restrict__ h, __nv_bfloat16* __restrict__ l)
{
    for (size_t i = (size_t)blockIdx.x * blockDim.x + threadIdx.x; i < n4;
         i += (size_t)gridDim.x * blockDim.x) {
        float4 v = ((const float4*)x)[i];
        __nv_bfloat16 h0 = __float2bfloat16(v.x);
        __nv_bfloat16 h1 = __float2bfloat16(v.y);
        __nv_bfloat16 h2 = __float2bfloat16(v.z);
        __nv_bfloat16 h3 = __float2bfloat16(v.w);
        __nv_bfloat162* hp = (__nv_bfloat162*)h;
        __nv_bfloat162* lp = (__nv_bfloat162*)l;
        hp[2*i]   = __nv_bfloat162(h0, h1);
        hp[2*i+1] = __nv_bfloat162(h2, h3);
        lp[2*i]   = __nv_bfloat162(__float2bfloat16(v.x - __bfloat162float(h0)),
                                   __float2bfloat16(v.y - __bfloat162float(h1)));
        lp[2*i+1] = __nv_bfloat162(__float2bfloat16(v.z - __bfloat162float(h2)),
                                   __float2bfloat16(v.w - __bfloat162float(h3)));
    }
}

// ----------------------- weight transpose + hi/lo split (generic) ------------
__global__ __launch_bounds__(256) void wt_trans_split_kernel(
    const float* __restrict__ W, int K, int N, int src0, int out_mul, int out_add,
    __nv_bfloat16* __restrict__ Th, __nv_bfloat16* __restrict__ Tl)
{
    __shared__ float tile[32][33];
    int nloc0 = blockIdx.x * 32, k0 = blockIdx.y * 32;
    int tx = threadIdx.x & 31, ty = threadIdx.x >> 5;
    #pragma unroll
    for (int r = ty; r < 32; r += 8) {
        int k = k0 + r, n = src0 + nloc0 + tx;
        tile[r][tx] = (k < K && n < N) ? W[(size_t)k * N + n] : 0.f;
    }
    __syncthreads();
    #pragma unroll
    for (int r = ty; r < 32; r += 8) {
        int nloc = nloc0 + r, k = k0 + tx;
        if (k < K && (src0 + nloc) < N) {
            float x = tile[tx][r];
            int outn = out_mul * nloc + out_add;
            __nv_bfloat16 hh = __float2bfloat16(x);
            Th[(size_t)outn * K + k] = hh;
            Tl[(size_t)outn * K + k] = __float2bfloat16(x - __bfloat162float(hh));
        }
    }
}

// ----------------------- mma primitives -------------------------------------
__device__ __forceinline__ void cp16(uint32_t dst, const void* src, uint32_t sz) {
    asm volatile("cp.async.cg.shared.global [%0], [%1], 16, %2;"
                 :: "r"(dst), "l"(src), "r"(sz) : "memory");
}
template<int NN> __device__ __forceinline__ void cpasync_wait() {
    asm volatile("cp.async.wait_group %0;" :: "n"(NN) : "memory");
}
__device__ __forceinline__ void ldsm_x4(uint32_t* r, uint32_t addr) {
    asm volatile("ldmatrix.sync.aligned.m8n8.x4.shared.b16 {%0,%1,%2,%3}, [%4];"
        : "=r"(r[0]), "=r"(r[1]), "=r"(r[2]), "=r"(r[3]) : "r"(addr));
}
__device__ __forceinline__ void mma_bf16(float* c, const uint32_t* a, const uint32_t* b) {
    asm volatile("mma.sync.aligned.m16n8k16.row.col.f32.bf16.bf16.f32 "
        "{%0,%1,%2,%3}, {%4,%5,%6,%7}, {%8,%9}, {%0,%1,%2,%3};"
        : "+f"(c[0]), "+f"(c[1]), "+f"(c[2]), "+f"(c[3])
        : "r"(a[0]), "r"(a[1]), "r"(a[2]), "r"(a[3]), "r"(b[0]), "r"(b[1]));
}

// ----------------------- mma.sync bf16x3 GEMM (2-stage, 1 sync/iter) --------
#define TC_STAGE_BYTES 40960
#define TC_SMEM_TOTAL  (2*TC_STAGE_BYTES)

__device__ __forceinline__ void tc_load_stage(
    uint32_t sbase,
    const __nv_bfloat16* __restrict__ Ah, const __nv_bfloat16* __restrict__ Al,
    const __nv_bfloat16* __restrict__ Bh, const __nv_bfloat16* __restrict__ Bl,
    int m0, int M, int n0, int K, int k0, int tid)
{
    #pragma unroll
    for (int i = 0; i < 2; i++) {
        int c = tid + i * 256;
        int row = c >> 2, kc = c & 3;
        uint32_t soff = (uint32_t)(row * 80 + kc * 16);
        size_t goffA = (size_t)(m0 + row) * K + k0 + kc * 8;
        uint32_t szA = ((m0 + row) < M) ? 16u : 0u;
        cp16(sbase + soff,         Ah + goffA, szA);
        cp16(sbase + 10240 + soff, Al + goffA, szA);
        size_t goffB = (size_t)(n0 + row) * K + k0 + kc * 8;
        cp16(sbase + 20480 + soff, Bh + goffB, 16u);
        cp16(sbase + 30720 + soff, Bl + goffB, 16u);
    }
    asm volatile("cp.async.commit_group;" ::: "memory");
}

// If ggh != nullptr: geglu epilogue (adjacent even/odd cols are (a, gate)).
__global__ __launch_bounds__(256, 2) void tc_gemm_kernel(
    const __nv_bfloat16* __restrict__ Ah, const __nv_bfloat16* __restrict__ Al,
    const __nv_bfloat16* __restrict__ Bh, const __nv_bfloat16* __restrict__ Bl,
    const float* __restrict__ bias, const float* __restrict__ res,
    float* __restrict__ C, int M, int N, int K, int slot,
    __nv_bfloat16* __restrict__ ggh, __nv_bfloat16* __restrict__ ggl)
{
    extern __shared__ char smem[];
    __shared__ float rmn[8], rmx[8];
    uint32_t sb = smem_to_u32(smem);
    int tid = threadIdx.x;
    int wid = tid >> 5, lane = tid & 31;
    int n0 = blockIdx.x * 128, m0 = blockIdx.y * 128;
    int wm = wid & 3, wn = wid >> 2;
    if (slot >= 0) slot += n0 / 1152;   // fused multi-tensor outputs

    float acc[2][8][4];
    #pragma unroll
    for (int mt = 0; mt < 2; mt++)
        #pragma unroll
        for (int nt = 0; nt < 8; nt++)
            #pragma unroll
            for (int e = 0; e < 4; e++) acc[mt][nt][e] = 0.f;

    const int KT = K >> 5;

    tc_load_stage(sb, Ah, Al, Bh, Bl, m0, M, n0, K, 0, tid);

    // one-sync pipeline: wait; sync (buf t ready, buf t+1 == buf t-1 drained);
    // prefetch t+1; compute t.
    for (int t = 0; t < KT; t++) {
        cpasync_wait<0>();
        __syncthreads();
        if (t + 1 < KT)
            tc_load_stage(sb + ((t + 1) & 1) * TC_STAGE_BYTES,
                          Ah, Al, Bh, Bl, m0, M, n0, K, (t + 1) << 5, tid);

        uint32_t base = sb + (t & 1) * TC_STAGE_BYTES;
        #pragma unroll
        for (int kk = 0; kk < 2; kk++) {
            uint32_t ah[2][4], al[2][4];
            #pragma unroll
            for (int mt = 0; mt < 2; mt++) {
                uint32_t arow = (uint32_t)(wm * 32 + mt * 16 + (lane & 15));
                uint32_t abyte = arow * 80 + kk * 32 + ((lane >> 4) << 4);
                ldsm_x4(ah[mt], base + abyte);
                ldsm_x4(al[mt], base + 10240 + abyte);
            }
            #pragma unroll
            for (int bp = 0; bp < 4; bp++) {
                uint32_t brow = (uint32_t)(wn * 64 + bp * 16 + (lane & 7) + (((lane >> 4) & 1) << 3));
                uint32_t bbyte = brow * 80 + kk * 32 + (((lane >> 3) & 1) << 4);
                uint32_t bh4[4], bl4[4];
                ldsm_x4(bh4, base + 20480 + bbyte);
                ldsm_x4(bl4, base + 30720 + bbyte);
                #pragma unroll
                for (int sub = 0; sub < 2; sub++)
                    #pragma unroll
                    for (int mt = 0; mt < 2; mt++)
                        mma_bf16(acc[mt][bp * 2 + sub], ah[mt], bh4 + sub * 2);
                #pragma unroll
                for (int sub = 0; sub < 2; sub++)
                    #pragma unroll
                    for (int mt = 0; mt < 2; mt++)
                        mma_bf16(acc[mt][bp * 2 + sub], ah[mt], bl4 + sub * 2);
                #pragma unroll
                for (int sub = 0; sub < 2; sub++)
                    #pragma unroll
                    for (int mt = 0; mt < 2; mt++)
                        mma_bf16(acc[mt][bp * 2 + sub], al[mt], bh4 + sub * 2);
            }
        }
    }

    if (ggh) {
        #pragma unroll
        for (int mt = 0; mt < 2; mt++) {
            int r0 = m0 + wm * 32 + mt * 16 + (lane >> 2);
            #pragma unroll
            for (int nt = 0; nt < 8; nt++) {
                int cc = n0 + wn * 64 + nt * 8 + (lane & 3) * 2;
                int gcol = cc >> 1;
                float ba = bias[gcol], bg = bias[gcol + FFD];
                #pragma unroll
                for (int h = 0; h < 2; h++) {
                    int r = r0 + h * 8;
                    if (r >= M) continue;
                    float a  = acc[mt][nt][h * 2]     + ba;
                    float gt = acc[mt][nt][h * 2 + 1] + bg;
                    float gl = 0.5f * gt * (1.f + erff(gt * 0.70710678118654752440f));
                    split_store(ggh, ggl, (size_t)r * FFD + gcol, a * gl);
                }
            }
        }
        return;
    }

    float mn = INFINITY, mx = -INFINITY;
    #pragma unroll
    for (int mt = 0; mt < 2; mt++) {
        int r0 = m0 + wm * 32 + mt * 16 + (lane >> 2);
        #pragma unroll
        for (int nt = 0; nt < 8; nt++) {
            int cc = n0 + wn * 64 + nt * 8 + (lane & 3) * 2;
            #pragma unroll
            for (int h = 0; h < 2; h++) {
                int r = r0 + h * 8;
                if (r >= M) continue;
                float2 o = make_float2(acc[mt][nt][h * 2], acc[mt][nt][h * 2 + 1]);
                if (bias) {
                    float2 bb = *(const float2*)(bias + cc);
                    o.x += bb.x; o.y += bb.y;
                }
                if (res) {
                    float2 rv = *(const float2*)(res + (size_t)r * N + cc);
                    o.x += rv.x; o.y += rv.y;
                }
                mn = fminf(mn, fminf(o.x, o.y));
                mx = fmaxf(mx, fmaxf(o.x, o.y));
                *(float2*)(C + (size_t)r * N + cc) = o;
            }
        }
    }

    if (slot >= 0) {
        for (int o = 16; o; o >>= 1) {
            mn = fminf(mn, __shfl_xor_sync(0xffffffffu, mn, o));
            mx = fmaxf(mx, __shfl_xor_sync(0xffffffffu, mx, o));
        }
        if (lane == 0) { rmn[wid] = mn; rmx[wid] = mx; }
        __syncthreads();
        if (tid == 0) {
            #pragma unroll
            for (int i = 1; i < 8; i++) { mn = fminf(mn, rmn[i]); mx = fmaxf(mx, rmx[i]); }
            mn = fminf(mn, rmn[0]); mx = fmaxf(mx, rmx[0]);
            atomicMinF(&g_stats[2 * slot], mn);
            atomicMaxF(&g_stats[2 * slot + 1], mx);
        }
    }
}

// ----------------------- stats init -----------------------------------------
__global__ void init_stats_kernel() {
    int t = threadIdx.x;
    if (t < 3) { g_stats[2 * t] = INFINITY; g_stats[2 * t + 1] = -INFINITY; }
    if (t == 3) g_stats[6] = 0.f;
}

// ----------------------- quantize to integer-bf16 ----------------------------
__global__ __launch_bounds__(256) void quant_qk_kernel(
    const float* __restrict__ x, int LDC, int colofs,
    __nv_bfloat16* __restrict__ out, int S, int SPAD, int slot)
{
    int bh = blockIdx.y, s0 = blockIdx.x * 32;
    int b = bh >> 4, h = bh & 15;
    float mn = g_stats[2 * slot], mx = g_stats[2 * slot + 1];
    float delta = (mx - mn) * (1.f / 255.f);
    float zp = rintf(-mn / delta);
    #pragma unroll
    for (int it = 0; it < 10; it++) {
        int local = threadIdx.x + it * 256;
        int sl = local / 80, d = local % 80;
        int s = s0 + sl;
        float val = 0.f;
        if (d < 72 && s < S) {
            float xv = x[((size_t)b * S + s) * LDC + colofs + h * HDIM + d];
            float q = fminf(fmaxf(rintf(xv / delta) + zp, 0.f), 255.f);
            val = q - zp;
        }
        out[((size_t)bh * SPAD + s) * 80 + d] = __float2bfloat16(val);
    }
}

// V: coalesced via 32x32 smem tile transpose.
__global__ __launch_bounds__(256) void quant_v_kernel(
    const float* __restrict__ x, int LDC, int colofs,
    __nv_bfloat16* __restrict__ out, int S, int SPAD, int slot)
{
    __shared__ float tile[32][33];
    int bh = blockIdx.y, s0 = blockIdx.x * 32;
    int b = bh >> 4, h = bh & 15;
    float mn = g_stats[2 * slot], mx = g_stats[2 * slot + 1];
    float delta = (mx - mn) * (1.f / 255.f);
    float zp = rintf(-mn / delta);
    int tx = threadIdx.x & 31, ty = threadIdx.x >> 5;

    for (int dc0 = 0; dc0 < 128; dc0 += 32) {
        #pragma unroll
        for (int r = ty; r < 32; r += 8) {
            int s = s0 + r, d = dc0 + tx;
            float val = 0.f;
            if (d < 72 && s < S) {
                float xv = x[((size_t)b * S + s) * LDC + colofs + h * HDIM + d];
                float q = fminf(fmaxf(rintf(xv / delta) + zp, 0.f), 255.f);
                val = q - zp;
            }
            tile[r][tx] = val;
        }
        __syncthreads();
        #pragma unroll
        for (int r = ty; r < 32; r += 8) {
            int d = dc0 + r;
            out[((size_t)bh * 128 + d) * SPAD + s0 + tx] = __float2bfloat16(tile[tx][r]);
        }
        __syncthreads();
    }
}

// ----------------------- pass 1: stats only (no score store) ----------------
__global__ __launch_bounds__(256) void stats_mma_kernel(int SK, int KROWS, float premul)
{
    __shared__ char sA[128 * 176];
    __shared__ char sB[128 * 176];
    int tid = threadIdx.x, wid = tid >> 5, lane = tid & 31;
    int bh = blockIdx.z;
    int kcol0 = blockIdx.x * 128, qrow0 = blockIdx.y * 128;
    int wm = wid & 3, wn = wid >> 2;
    uint32_t sa = smem_to_u32(sA), sb = smem_to_u32(sB);

    const __nv_bfloat16* qb = g_qi + ((size_t)bh * 1024 + qrow0) * 80;
    const __nv_bfloat16* kb = g_ki + ((size_t)bh * KROWS + kcol0) * 80;
    #pragma unroll
    for (int i = 0; i < 5; i++) {
        int c = tid + i * 256;
        int row = c / 10, j = c - row * 10;
        cp16(sa + row * 176 + j * 16, qb + (size_t)row * 80 + j * 8, 16u);
        cp16(sb + row * 176 + j * 16, kb + (size_t)row * 80 + j * 8, 16u);
    }
    asm volatile("cp.async.commit_group;" ::: "memory");
    cpasync_wait<0>();
    __syncthreads();

    float acc[2][8][4];
    #pragma unroll
    for (int mt = 0; mt < 2; mt++)
        #pragma unroll
        for (int nt = 0; nt < 8; nt++)
            #pragma unroll
            for (int e = 0; e < 4; e++) acc[mt][nt][e] = 0.f;

    #pragma unroll
    for (int kk = 0; kk < 5; kk++) {
        uint32_t af[2][4];
        #pragma unroll
        for (int mt = 0; mt < 2; mt++) {
            uint32_t arow = (uint32_t)(wm * 32 + mt * 16 + (lane & 15));
            ldsm_x4(af[mt], sa + arow * 176 + kk * 32 + ((lane >> 4) << 4));
        }
        #pragma unroll
        for (int bp = 0; bp < 4; bp++) {
            uint32_t brow = (uint32_t)(wn * 64 + bp * 16 + (lane & 7) + (((lane >> 4) & 1) << 3));
            uint32_t bf4[4];
            ldsm_x4(bf4, sb + brow * 176 + kk * 32 + (((lane >> 3) & 1) << 4));
            #pragma unroll
            for (int sub = 0; sub < 2; sub++) {
                int nt = bp * 2 + sub;
                #pragma unroll
                for (int mt = 0; mt < 2; mt++)
                    mma_bf16(acc[mt][nt], af[mt], bf4 + sub * 2);
            }
        }
    }

    float dq = (g_stats[1] - g_stats[0]) * (1.f / 255.f);
    float dk = (g_stats[3] - g_stats[2]) * (1.f / 255.f);
    float sc = dq * dk * premul;

    #pragma unroll
    for (int mt = 0; mt < 2; mt++) {
        #pragma unroll
        for (int h2 = 0; h2 < 2; h2++) {
            int r = qrow0 + wm * 32 + mt * 16 + (lane >> 2) + h2 * 8;
            float zs = 0.f, mxv = -INFINITY;
            #pragma unroll
            for (int nt = 0; nt < 8; nt++) {
                int c0 = kcol0 + wn * 64 + nt * 8 + (lane & 3) * 2;
                float v0 = acc[mt][nt][h2 * 2]     * sc;
                float v1 = acc[mt][nt][h2 * 2 + 1] * sc;
                if (c0 < SK)     { zs += fexp(v0); mxv = fmaxf(mxv, v0); }
                if (c0 + 1 < SK) { zs += fexp(v1); mxv = fmaxf(mxv, v1); }
            }
            #pragma unroll
            for (int o = 1; o <= 2; o <<= 1) {
                zs  += __shfl_xor_sync(0xffffffffu, zs, o);
                mxv = fmaxf(mxv, __shfl_xor_sync(0xffffffffu, mxv, o));
            }
            if ((lane & 3) == 0) {
                size_t prow = ((size_t)bh * SEQ + r) * 16 + blockIdx.x * 2 + wn;
                g_partZ[prow] = zs;
                g_partM[prow] = mxv;
            }
        }
    }
}

// ----------------------- row reduce: Z, pmax (deterministic) ----------------
__global__ __launch_bounds__(256) void rowreduce_kernel(int nparts) {
    int row = blockIdx.x * 256 + threadIdx.x;
    if (row >= NROWSBH) return;
    float Z = 0.f, M = -INFINITY;
    const float* pz = g_partZ + (size_t)row * 16;
    const float* pm = g_partM + (size_t)row * 16;
    for (int j = 0; j < nparts; j++) { Z += pz[j]; M = fmaxf(M, pm[j]); }
    g_rowZ[row] = Z;
    float pr = fexp(M) / Z;
    for (int o = 16; o; o >>= 1) pr = fmaxf(pr, __shfl_xor_sync(0xffffffffu, pr, o));
    __shared__ float sh[8];
    if ((threadIdx.x & 31) == 0) sh[threadIdx.x >> 5] = pr;
    __syncthreads();
    if (threadIdx.x == 0) {
        for (int i = 1; i < 8; i++) pr = fmaxf(pr, sh[i]);
        atomicMaxF(&g_stats[6], pr);
    }
}

// ----------------------- pass 2: fused flash-style attention ----------------
#define PV2_Q   0
#define PV2_K   22528
#define PV2_V   45056
#define PV2_P   81920
#define PV2_SC  100352
#define PV2_SMEM 100864

__global__ __launch_bounds__(256, 2) void pv2_kernel(
    __nv_bfloat16* __restrict__ oh, __nv_bfloat16* __restrict__ ol,
    int SK, int SKPAD, float premul)
{
    extern __shared__ char smem[];
    uint32_t sb = smem_to_u32(smem);
    float* sscale = (float*)(smem + PV2_SC);
    int tid = threadIdx.x, wid = tid >> 5, lane = tid & 31;
    int bh = blockIdx.y, m0 = blockIdx.x * 128;
    int b = bh >> 4, h = bh & 15;
    int wm = wid & 3, wn = wid >> 2;
    size_t rowbase = (size_t)bh * SEQ + m0;

    const __nv_bfloat16* qb = g_qi + ((size_t)bh * SEQ + m0) * 80;
    const __nv_bfloat16* kb = g_ki + (size_t)bh * SKPAD * 80;
    const __nv_bfloat16* vb = g_vi + (size_t)bh * 128 * SKPAD;
    const int KT = SKPAD >> 6;

    float pmax = g_stats[6];
    if (tid < 128)
        sscale[tid] = 255.f / (g_rowZ[rowbase + tid] * pmax);

    float dq = (g_stats[1] - g_stats[0]) * (1.f / 255.f);
    float dk = (g_stats[3] - g_stats[2]) * (1.f / 255.f);
    float sc = dq * dk * premul;

    #pragma unroll
    for (int i = 0; i < 5; i++) {
        int c = tid + i * 256;
        int row = c / 10, j = c - row * 10;
        cp16(sb + PV2_Q + row * 176 + j * 16, qb + (size_t)row * 80 + j * 8, 16u);
    }
    #pragma unroll
    for (int i = 0; i < 3; i++) {
        int c = tid + i * 256;
        if (c < 640) {
            int row = c / 10, j = c - row * 10;
            cp16(sb + PV2_K + row * 176 + j * 16, kb + (size_t)row * 80 + j * 8, 16u);
        }
    }
    #pragma unroll
    for (int i = 0; i < 4; i++) {
        int c = tid + i * 256;
        int row = c >> 3, j = c & 7;
        cp16(sb + PV2_V + row * 144 + j * 16, vb + (size_t)row * SKPAD + j * 8, 16u);
    }
    asm volatile("cp.async.commit_group;" ::: "memory");

    float acc_o[2][8][4];
    #pragma unroll
    for (int mt = 0; mt < 2; mt++)
        #pragma unroll
        for (int nt = 0; nt < 8; nt++)
            #pragma unroll
            for (int e = 0; e < 4; e++) acc_o[mt][nt][e] = 0.f;

    // two-sync pipeline: wait; sync1 (K/V(t) ready, buf t+1 == buf t-1 drained
    // since all warps finished PV(t-1) before reaching sync1); prefetch t+1;
    // QK; P-write; sync2; PV.
    for (int t = 0; t < KT; t++) {
        cpasync_wait<0>();
        __syncthreads();
        if (t + 1 < KT) {
            uint32_t kbuf = sb + PV2_K + ((t + 1) & 1) * 11264;
            uint32_t vbuf = sb + PV2_V + ((t + 1) & 1) * 18432;
            const __nv_bfloat16* kg = kb + (size_t)(t + 1) * 64 * 80;
            const __nv_bfloat16* vg = vb + (size_t)(t + 1) * 64;
            #pragma unroll
            for (int i = 0; i < 3; i++) {
                int c = tid + i * 256;
                if (c < 640) {
                    int row = c / 10, j = c - row * 10;
                    cp16(kbuf + row * 176 + j * 16, kg + (size_t)row * 80 + j * 8, 16u);
                }
            }
            #pragma unroll
            for (int i = 0; i < 4; i++) {
                int c = tid + i * 256;
                int row = c >> 3, j = c & 7;
                cp16(vbuf + row * 144 + j * 16, vg + (size_t)row * SKPAD + j * 8, 16u);
            }
            asm volatile("cp.async.commit_group;" ::: "memory");
        }

        uint32_t kbase = sb + PV2_K + (t & 1) * 11264;
        uint32_t vbase = sb + PV2_V + (t & 1) * 18432;

        float acc_s[2][4][4];
        #pragma unroll
        for (int mt = 0; mt < 2; mt++)
            #pragma unroll
            for (int nt = 0; nt < 4; nt++)
                #pragma unroll
                for (int e = 0; e < 4; e++) acc_s[mt][nt][e] = 0.f;

        #pragma unroll
        for (int kk = 0; kk < 5; kk++) {
            uint32_t af[2][4];
            #pragma unroll
            for (int mt = 0; mt < 2; mt++) {
                uint32_t arow = (uint32_t)(wm * 32 + mt * 16 + (lane & 15));
                ldsm_x4(af[mt], sb + PV2_Q + arow * 176 + kk * 32 + ((lane >> 4) << 4));
            }
            #pragma unroll
            for (int bp = 0; bp < 2; bp++) {
                uint32_t brow = (uint32_t)(wn * 32 + bp * 16 + (lane & 7) + (((lane >> 4) & 1) << 3));
                uint32_t bf4[4];
                ldsm_x4(bf4, kbase + brow * 176 + kk * 32 + (((lane >> 3) & 1) << 4));
                #pragma unroll
                for (int sub = 0; sub < 2; sub++) {
                    int nt = bp * 2 + sub;
                    #pragma unroll
                    for (int mt = 0; mt < 2; mt++)
                        mma_bf16(acc_s[mt][nt], af[mt], bf4 + sub * 2);
                }
            }
        }

        #pragma unroll
        for (int mt = 0; mt < 2; mt++) {
            #pragma unroll
            for (int h2 = 0; h2 < 2; h2++) {
                int rl = wm * 32 + mt * 16 + (lane >> 2) + h2 * 8;
                float rsc = sscale[rl];
                #pragma unroll
                for (int nt = 0; nt < 4; nt++) {
                    int kcl = wn * 32 + nt * 8 + (lane & 3) * 2;
                    int kcg = t * 64 + kcl;
                    float p0 = 0.f, p1 = 0.f;
                    if (kcg < SK)
                        p0 = fminf(rintf(fexp(acc_s[mt][nt][h2 * 2] * sc) * rsc), 255.f);
                    if (kcg + 1 < SK)
                        p1 = fminf(rintf(fexp(acc_s[mt][nt][h2 * 2 + 1] * sc) * rsc), 255.f);
                    *(__nv_bfloat162*)(smem + PV2_P + rl * 144 + kcl * 2) =
                        __nv_bfloat162(__float2bfloat16(p0), __float2bfloat16(p1));
                }
            }
        }
        __syncthreads();   // P complete

        #pragma unroll
        for (int kk = 0; kk < 4; kk++) {
            uint32_t af[2][4];
            #pragma unroll
            for (int mt = 0; mt < 2; mt++) {
                uint32_t arow = (uint32_t)(wm * 32 + mt * 16 + (lane & 15));
                ldsm_x4(af[mt], sb + PV2_P + arow * 144 + kk * 32 + ((lane >> 4) << 4));
            }
            int bplim = (wn == 0) ? 4 : 1;
            for (int bp = 0; bp < bplim; bp++) {
                uint32_t brow = (uint32_t)(wn * 64 + bp * 16 + (lane & 7) + (((lane >> 4) & 1) << 3));
                uint32_t bf4[4];
                ldsm_x4(bf4, vbase + brow * 144 + kk * 32 + (((lane >> 3) & 1) << 4));
                #pragma unroll
                for (int sub = 0; sub < 2; sub++) {
                    int nt = bp * 2 + sub;
                    #pragma unroll
                    for (int mt = 0; mt < 2; mt++)
                        mma_bf16(acc_o[mt][nt], af[mt], bf4 + sub * 2);
                }
            }
        }
    }

    float dp = pmax * (1.f / 255.f);
    float dv = (g_stats[5] - g_stats[4]) * (1.f / 255.f);
    float osc = dp * dv;

    #pragma unroll
    for (int mt = 0; mt < 2; mt++) {
        int r0 = m0 + wm * 32 + mt * 16 + (lane >> 2);
        #pragma unroll
        for (int nt = 0; nt < 8; nt++) {
            int n = wn * 64 + nt * 8 + (lane & 3) * 2;
            if (n >= 72) continue;
            #pragma unroll
            for (int h2 = 0; h2 < 2; h2++) {
                int r = r0 + h2 * 8;
                size_t idx = ((size_t)b * SEQ + r) * DMODEL + h * HDIM + n;
                split_store(oh, ol, idx,     acc_o[mt][nt][h2 * 2]     * osc);
                split_store(oh, ol, idx + 1, acc_o[mt][nt][h2 * 2 + 1] * osc);
            }
        }
    }
}

// ----------------------- host orchestration ---------------------------------
static void tc_gemm(const __nv_bfloat16* ah, const __nv_bfloat16* al,
                    const __nv_bfloat16* bh, const __nv_bfloat16* bl,
                    const float* bias, const float* res,
                    float* C, int M, int N, int K, int slot = -1,
                    __nv_bfloat16* ggh = nullptr, __nv_bfloat16* ggl = nullptr) {
    static bool attr_set = false;
    if (!attr_set) {
        cudaFuncSetAttribute(tc_gemm_kernel, cudaFuncAttributeMaxDynamicSharedMemorySize,
                             TC_SMEM_TOTAL);
        cudaFuncSetAttribute(pv2_kernel, cudaFuncAttributeMaxDynamicSharedMemorySize,
                             PV2_SMEM);
        attr_set = true;
    }
    dim3 grid(N / 128, (M + 127) / 128);
    tc_gemm_kernel<<<grid, 256, TC_SMEM_TOTAL>>>(ah, al, bh, bl,
                                                 bias, res, C, M, N, K, slot, ggh, ggl);
}

static void trans_W(const float* W, int K, int N, __nv_bfloat16* Th, __nv_bfloat16* Tl) {
    wt_trans_split_kernel<<<dim3(N / 32, K / 32), 256>>>(W, K, N, 0, 1, 0, Th, Tl);
}

extern "C" void kernel_launch(void* const* d_in, const int* in_sizes, int n_in,
                              void* d_out, int out_size) {
    (void)in_sizes; (void)n_in; (void)out_size;
    const float* hs    = (const float*)d_in[0];
    const float* enc   = (const float*)d_in[1];
    const float* ln1g  = (const float*)d_in[2];
    const float* ln1b  = (const float*)d_in[3];
    const float* Wq1   = (const float*)d_in[4];
    const float* Wk1   = (const float*)d_in[5];
    const float* Wv1   = (const float*)d_in[6];
    const float* Wo1   = (const float*)d_in[7];
    const float* bo1   = (const float*)d_in[8];
    const float* ln2g  = (const float*)d_in[9];
    const float* ln2b  = (const float*)d_in[10];
    const float* Wq2   = (const float*)d_in[11];
    const float* Wk2   = (const float*)d_in[12];
    const float* Wv2   = (const float*)d_in[13];
    const float* Wo2   = (const float*)d_in[14];
    const float* bo2   = (const float*)d_in[15];
    const float* ln3g  = (const float*)d_in[16];
    const float* ln3b  = (const float*)d_in[17];
    const float* Wff1  = (const float*)d_in[18];
    const float* bff1  = (const float*)d_in[19];
    const float* Wff2  = (const float*)d_in[20];
    const float* bff2  = (const float*)d_in[21];
    float* out = (float*)d_out;

    void* p;
    cudaGetSymbolAddress(&p, g_q);      float* q_  = (float*)p;
    cudaGetSymbolAddress(&p, g_proj);   float* pj_ = (float*)p;
    __nv_bfloat16 *ah_, *al_, *gh_, *gl_, *bh_, *bl_;
    cudaGetSymbolAddress(&p, g_ah);   ah_ = (__nv_bfloat16*)p;
    cudaGetSymbolAddress(&p, g_al);   al_ = (__nv_bfloat16*)p;
    cudaGetSymbolAddress(&p, g_gh);   gh_ = (__nv_bfloat16*)p;
    cudaGetSymbolAddress(&p, g_gl);   gl_ = (__nv_bfloat16*)p;
    cudaGetSymbolAddress(&p, g_bh);   bh_ = (__nv_bfloat16*)p;
    cudaGetSymbolAddress(&p, g_bl);   bl_ = (__nv_bfloat16*)p;
    __nv_bfloat16 *qi_, *ki_, *vi_;
    cudaGetSymbolAddress(&p, g_qi);   qi_ = (__nv_bfloat16*)p;
    cudaGetSymbolAddress(&p, g_ki);   ki_ = (__nv_bfloat16*)p;
    cudaGetSymbolAddress(&p, g_vi);   vi_ = (__nv_bfloat16*)p;

    const float premul = 1.0f / sqrtf((float)HDIM);
    const size_t nE = (size_t)ENCROWS * DMODEL;
    const size_t WSTRIDE = (size_t)DMODEL * DMODEL;

    // ================= self-attention (fused QKV GEMM) =================
    init_stats_kernel<<<1, 32>>>();
    ln_split_kernel<<<ROWS, 256>>>(hs, ln1g, ln1b, ah_, al_);
    trans_W(Wq1, DMODEL, DMODEL, bh_,               bl_);
    trans_W(Wk1, DMODEL, DMODEL, bh_ + WSTRIDE,     bl_ + WSTRIDE);
    trans_W(Wv1, DMODEL, DMODEL, bh_ + 2 * WSTRIDE, bl_ + 2 * WSTRIDE);
    tc_gemm(ah_, al_, bh_, bl_, nullptr, nullptr, pj_, ROWS, 3456, DMODEL, 0);
    quant_qk_kernel<<<dim3(32, BH), 256>>>(pj_, 3456, 0,    qi_, SEQ, 1024, 0);
    quant_qk_kernel<<<dim3(32, BH), 256>>>(pj_, 3456, 1152, ki_, SEQ, 1024, 1);
    quant_v_kernel<<<dim3(32, BH), 256>>>(pj_, 3456, 2304, vi_, SEQ, 1024, 2);
    stats_mma_kernel<<<dim3(8, 8, BH), 256>>>(SEQ, 1024, premul);
    rowreduce_kernel<<<NROWSBH / 256, 256>>>(16);
    pv2_kernel<<<dim3(8, BH), 256, PV2_SMEM>>>(ah_, al_, SEQ, 1024, premul);
    trans_W(Wo1, DMODEL, DMODEL, bh_, bl_);
    tc_gemm(ah_, al_, bh_, bl_, bo1, hs, out, ROWS, DMODEL, DMODEL);

    // ================= cross-attention (fused KV GEMM) =================
    init_stats_kernel<<<1, 32>>>();
    ln_split_kernel<<<ROWS, 256>>>(out, ln2g, ln2b, ah_, al_);
    trans_W(Wq2, DMODEL, DMODEL, bh_, bl_);
    tc_gemm(ah_, al_, bh_, bl_, nullptr, nullptr, q_, ROWS, DMODEL, DMODEL, 0);
    convert_split_kernel<<<2048, 256>>>(enc, nE / 4, ah_, al_);
    trans_W(Wk2, DMODEL, DMODEL, bh_,           bl_);
    trans_W(Wv2, DMODEL, DMODEL, bh_ + WSTRIDE, bl_ + WSTRIDE);
    tc_gemm(ah_, al_, bh_, bl_, nullptr, nullptr, pj_, ENCROWS, 2304, DMODEL, 1);
    quant_qk_kernel<<<dim3(32, BH), 256>>>(q_, 1152, 0,    qi_, SEQ, 1024, 0);
    quant_qk_kernel<<<dim3(4, BH), 256>>>(pj_, 2304, 0,    ki_, SENC, 128, 1);
    quant_v_kernel<<<dim3(4, BH), 256>>>(pj_, 2304, 1152, vi_, SENC, 128, 2);
    stats_mma_kernel<<<dim3(1, 8, BH), 256>>>(SENC, 128, premul);
    rowreduce_kernel<<<NROWSBH / 256, 256>>>(2);
    pv2_kernel<<<dim3(8, BH), 256, PV2_SMEM>>>(ah_, al_, SENC, 128, premul);
    trans_W(Wo2, DMODEL, DMODEL, bh_, bl_);
    tc_gemm(ah_, al_, bh_, bl_, bo2, out, out, ROWS, DMODEL, DMODEL);

    // ================= feed-forward (GEGLU fused into FF1 epilogue) =========
    ln_split_kernel<<<ROWS, 256>>>(out, ln3g, ln3b, ah_, al_);
    wt_trans_split_kernel<<<dim3(FFD / 32, DMODEL / 32), 256>>>(
        Wff1, DMODEL, 2 * FFD, 0,   2, 0, bh_, bl_);
    wt_trans_split_kernel<<<dim3(FFD / 32, DMODEL / 32), 256>>>(
        Wff1, DMODEL, 2 * FFD, FFD, 2, 1, bh_, bl_);
    tc_gemm(ah_, al_, bh_, bl_, bff1, nullptr, nullptr, ROWS, 2 * FFD, DMODEL, -1,
            gh_, gl_);
    trans_W(Wff2, FFD, DMODEL, bh_, bl_);
    tc_gemm(gh_, gl_, bh_, bl_, bff2, out, out, ROWS, DMODEL, FFD);
}

// round 16
// speedup vs baseline: 1.0125x; 1.0125x over previous
#include <cuda_runtime.h>
#include <cuda_bf16.h>
#include <math.h>
#include <stdint.h>

// Problem dims
#define BATCH   8
#define SEQ     1024
#define DMODEL  1152
#define NHEAD   16
#define HDIM    72
#define SENC    77
#define FFD     4608
#define ROWS    (BATCH*SEQ)        // 8192
#define ENCROWS (BATCH*SENC)       // 616
#define BH      (BATCH*NHEAD)      // 128
#define NROWSBH (BH*SEQ)           // 131072

__device__ __forceinline__ uint32_t smem_to_u32(const void* smem_ptr) {
    uint32_t addr;
    asm("{ .reg .u64 tmp; cvta.to.shared.u64 tmp, %1; cvt.u32.u64 %0, tmp; }"
        : "=r"(addr) : "l"(smem_ptr));
    return addr;
}

// fast exp on the FMA pipe (no MUFU). rel err ~2e-7.
__device__ __forceinline__ float fexp(float x) {
    float t = x * 1.4426950408889634f;
    t = fmaxf(t, -126.0f);
    float fi = floorf(t);
    float f = t - fi;
    float p = 1.3333558146e-3f;
    p = fmaf(p, f, 9.6181291076e-3f);
    p = fmaf(p, f, 5.5504108664e-2f);
    p = fmaf(p, f, 2.4022650695910e-1f);
    p = fmaf(p, f, 6.9314718055994e-1f);
    p = fmaf(p, f, 1.0f);
    return p * __int_as_float(((int)fi + 127) << 23);
}

__device__ __forceinline__ void split_store(
    __nv_bfloat16* __restrict__ h, __nv_bfloat16* __restrict__ l,
    size_t idx, float v)
{
    __nv_bfloat16 hh = __float2bfloat16(v);
    h[idx] = hh;
    l[idx] = __float2bfloat16(v - __bfloat162float(hh));
}

// ----------------------- scratch (device globals; no runtime alloc) ---------
__device__ float g_q[(size_t)ROWS*DMODEL];
__device__ float g_rowZ[NROWSBH];
__device__ float g_partZ[(size_t)NROWSBH*16];
__device__ float g_partM[(size_t)NROWSBH*16];
__device__ float g_proj[(size_t)ROWS*3456];          // fused QKV / KV outputs
__device__ float g_stats[8];
// bf16 hi/lo operand buffers (weight GEMMs)
__device__ __nv_bfloat16 g_ah[(size_t)ROWS*DMODEL];
__device__ __nv_bfloat16 g_al[(size_t)ROWS*DMODEL];
__device__ __nv_bfloat16 g_gh[(size_t)ROWS*FFD];     // geglu output (FF2 A operand)
__device__ __nv_bfloat16 g_gl[(size_t)ROWS*FFD];
__device__ __nv_bfloat16 g_bh[(size_t)(2*FFD)*DMODEL];
__device__ __nv_bfloat16 g_bl[(size_t)(2*FFD)*DMODEL];
// integer-bf16 attention operands
__device__ __nv_bfloat16 g_qi[(size_t)BH*1024*80];
__device__ __nv_bfloat16 g_ki[(size_t)BH*1024*80];
__device__ __nv_bfloat16 g_vi[(size_t)BH*128*1024];

// ----------------------- atomic float min/max -------------------------------
__device__ __forceinline__ void atomicMaxF(float* a, float v) {
    if (v >= 0.f) atomicMax((int*)a, __float_as_int(v));
    else          atomicMin((unsigned int*)a, __float_as_uint(v));
}
__device__ __forceinline__ void atomicMinF(float* a, float v) {
    if (v >= 0.f) atomicMin((int*)a, __float_as_int(v));
    else          atomicMax((unsigned int*)a, __float_as_uint(v));
}

// ----------------------- LayerNorm -> bf16 hi/lo -----------------------------
__global__ __launch_bounds__(256) void ln_split_kernel(
    const float* __restrict__ x, const float* __restrict__ g,
    const float* __restrict__ b,
    __nv_bfloat16* __restrict__ oh, __nv_bfloat16* __restrict__ ol)
{
    const int N = DMODEL;
    size_t row = blockIdx.x;
    const float* xr = x + row * N;
    int tid = threadIdx.x;

    float lv[5];
    int cnt = 0;
    float s = 0.f;
    for (int i = tid; i < N; i += 256) { float t = xr[i]; lv[cnt++] = t; s += t; }

    __shared__ float sh[8];
    for (int ofs = 16; ofs; ofs >>= 1) s += __shfl_xor_sync(0xffffffffu, s, ofs);
    if ((tid & 31) == 0) sh[tid >> 5] = s;
    __syncthreads();
    float tot = 0.f;
    #pragma unroll
    for (int i = 0; i < 8; i++) tot += sh[i];
    float mu = tot * (1.f / (float)N);

    float vs = 0.f;
    for (int c = 0; c < cnt; c++) { float d = lv[c] - mu; vs += d * d; }
    __syncthreads();
    for (int ofs = 16; ofs; ofs >>= 1) vs += __shfl_xor_sync(0xffffffffu, vs, ofs);
    if ((tid & 31) == 0) sh[tid >> 5] = vs;
    __syncthreads();
    float vtot = 0.f;
    #pragma unroll
    for (int i = 0; i < 8; i++) vtot += sh[i];
    float inv = rsqrtf(vtot * (1.f / (float)N) + 1e-5f);

    int i = tid;
    for (int c = 0; c < cnt; c++, i += 256) {
        float val = (lv[c] - mu) * inv * g[i] + b[i];
        split_store(oh, ol, row * N + i, val);
    }
}

// ----------------------- fp32 -> bf16 hi/lo split (for enc) -----------------
__global__ __launch_bounds__(256) void convert_split_kernel(
    const float* __restrict__ x, size_t n4,
    __nv_bfloat16* __restrict__ h, __nv_bfloat16* __restrict__ l)
{
    for (size_t i = (size_t)blockIdx.x * blockDim.x + threadIdx.x; i < n4;
         i += (size_t)gridDim.x * blockDim.x) {
        float4 v = ((const float4*)x)[i];
        __nv_bfloat16 h0 = __float2bfloat16(v.x);
        __nv_bfloat16 h1 = __float2bfloat16(v.y);
        __nv_bfloat16 h2 = __float2bfloat16(v.z);
        __nv_bfloat16 h3 = __float2bfloat16(v.w);
        __nv_bfloat162* hp = (__nv_bfloat162*)h;
        __nv_bfloat162* lp = (__nv_bfloat162*)l;
        hp[2*i]   = __nv_bfloat162(h0, h1);
        hp[2*i+1] = __nv_bfloat162(h2, h3);
        lp[2*i]   = __nv_bfloat162(__float2bfloat16(v.x - __bfloat162float(h0)),
                                   __float2bfloat16(v.y - __bfloat162float(h1)));
        lp[2*i+1] = __nv_bfloat162(__float2bfloat16(v.z - __bfloat162float(h2)),
                                   __float2bfloat16(v.w - __bfloat162float(h3)));
    }
}

// ----------------------- weight transpose + hi/lo split (multi-z) ------------
// z selects weight pointer, source col base (src0 + z*src_step), output row
// offset (out_mul*nloc + z*out_add_step), output buffer offset (z*outstride).
__global__ __launch_bounds__(256) void wt_trans_split_kernel(
    const float* __restrict__ W0, const float* __restrict__ W1,
    const float* __restrict__ W2,
    int K, int N, int src0, int src_step, int out_mul, int out_add_step,
    __nv_bfloat16* __restrict__ Th, __nv_bfloat16* __restrict__ Tl,
    size_t outstride)
{
    __shared__ float tile[32][33];
    int z = blockIdx.z;
    const float* W = (z == 0) ? W0 : ((z == 1) ? W1 : W2);
    int src = src0 + z * src_step;
    int oadd = z * out_add_step;
    Th += (size_t)z * outstride;
    Tl += (size_t)z * outstride;
    int nloc0 = blockIdx.x * 32, k0 = blockIdx.y * 32;
    int tx = threadIdx.x & 31, ty = threadIdx.x >> 5;
    #pragma unroll
    for (int r = ty; r < 32; r += 8) {
        int k = k0 + r, n = src + nloc0 + tx;
        tile[r][tx] = (k < K && n < N) ? W[(size_t)k * N + n] : 0.f;
    }
    __syncthreads();
    #pragma unroll
    for (int r = ty; r < 32; r += 8) {
        int nloc = nloc0 + r, k = k0 + tx;
        if (k < K && (src + nloc) < N) {
            float x = tile[tx][r];
            int outn = out_mul * nloc + oadd;
            __nv_bfloat16 hh = __float2bfloat16(x);
            Th[(size_t)outn * K + k] = hh;
            Tl[(size_t)outn * K + k] = __float2bfloat16(x - __bfloat162float(hh));
        }
    }
}

// ----------------------- mma primitives -------------------------------------
__device__ __forceinline__ void cp16(uint32_t dst, const void* src, uint32_t sz) {
    asm volatile("cp.async.cg.shared.global [%0], [%1], 16, %2;"
                 :: "r"(dst), "l"(src), "r"(sz) : "memory");
}
template<int NN> __device__ __forceinline__ void cpasync_wait() {
    asm volatile("cp.async.wait_group %0;" :: "n"(NN) : "memory");
}
__device__ __forceinline__ void ldsm_x4(uint32_t* r, uint32_t addr) {
    asm volatile("ldmatrix.sync.aligned.m8n8.x4.shared.b16 {%0,%1,%2,%3}, [%4];"
        : "=r"(r[0]), "=r"(r[1]), "=r"(r[2]), "=r"(r[3]) : "r"(addr));
}
__device__ __forceinline__ void mma_bf16(float* c, const uint32_t* a, const uint32_t* b) {
    asm volatile("mma.sync.aligned.m16n8k16.row.col.f32.bf16.bf16.f32 "
        "{%0,%1,%2,%3}, {%4,%5,%6,%7}, {%8,%9}, {%0,%1,%2,%3};"
        : "+f"(c[0]), "+f"(c[1]), "+f"(c[2]), "+f"(c[3])
        : "r"(a[0]), "r"(a[1]), "r"(a[2]), "r"(a[3]), "r"(b[0]), "r"(b[1]));
}

// ----------------------- mma.sync bf16x3 GEMM (2-stage, 2 CTAs/SM) ----------
// R14 form: prefetch issued BEFORE wait<1> (early load slack), 2 syncs/iter.
#define TC_STAGE_BYTES 40960
#define TC_SMEM_TOTAL  (2*TC_STAGE_BYTES)

__device__ __forceinline__ void tc_load_stage(
    uint32_t sbase,
    const __nv_bfloat16* __restrict__ Ah, const __nv_bfloat16* __restrict__ Al,
    const __nv_bfloat16* __restrict__ Bh, const __nv_bfloat16* __restrict__ Bl,
    int m0, int M, int n0, int K, int k0, int tid)
{
    #pragma unroll
    for (int i = 0; i < 2; i++) {
        int c = tid + i * 256;
        int row = c >> 2, kc = c & 3;
        uint32_t soff = (uint32_t)(row * 80 + kc * 16);
        size_t goffA = (size_t)(m0 + row) * K + k0 + kc * 8;
        uint32_t szA = ((m0 + row) < M) ? 16u : 0u;
        cp16(sbase + soff,         Ah + goffA, szA);
        cp16(sbase + 10240 + soff, Al + goffA, szA);
        size_t goffB = (size_t)(n0 + row) * K + k0 + kc * 8;
        cp16(sbase + 20480 + soff, Bh + goffB, 16u);
        cp16(sbase + 30720 + soff, Bl + goffB, 16u);
    }
    asm volatile("cp.async.commit_group;" ::: "memory");
}

// If ggh != nullptr: geglu epilogue (adjacent even/odd cols are (a, gate)).
__global__ __launch_bounds__(256, 2) void tc_gemm_kernel(
    const __nv_bfloat16* __restrict__ Ah, const __nv_bfloat16* __restrict__ Al,
    const __nv_bfloat16* __restrict__ Bh, const __nv_bfloat16* __restrict__ Bl,
    const float* __restrict__ bias, const float* __restrict__ res,
    float* __restrict__ C, int M, int N, int K, int slot,
    __nv_bfloat16* __restrict__ ggh, __nv_bfloat16* __restrict__ ggl)
{
    extern __shared__ char smem[];
    __shared__ float rmn[8], rmx[8];
    uint32_t sb = smem_to_u32(smem);
    int tid = threadIdx.x;
    int wid = tid >> 5, lane = tid & 31;
    int n0 = blockIdx.x * 128, m0 = blockIdx.y * 128;
    int wm = wid & 3, wn = wid >> 2;
    if (slot >= 0) slot += n0 / 1152;   // fused multi-tensor outputs

    float acc[2][8][4];
    #pragma unroll
    for (int mt = 0; mt < 2; mt++)
        #pragma unroll
        for (int nt = 0; nt < 8; nt++)
            #pragma unroll
            for (int e = 0; e < 4; e++) acc[mt][nt][e] = 0.f;

    const int KT = K >> 5;

    tc_load_stage(sb, Ah, Al, Bh, Bl, m0, M, n0, K, 0, tid);

    for (int t = 0; t < KT; t++) {
        if (t + 1 < KT) {
            tc_load_stage(sb + ((t + 1) & 1) * TC_STAGE_BYTES,
                          Ah, Al, Bh, Bl, m0, M, n0, K, (t + 1) << 5, tid);
            cpasync_wait<1>();
        } else {
            cpasync_wait<0>();
        }
        __syncthreads();

        uint32_t base = sb + (t & 1) * TC_STAGE_BYTES;
        #pragma unroll
        for (int kk = 0; kk < 2; kk++) {
            uint32_t ah[2][4], al[2][4];
            #pragma unroll
            for (int mt = 0; mt < 2; mt++) {
                uint32_t arow = (uint32_t)(wm * 32 + mt * 16 + (lane & 15));
                uint32_t abyte = arow * 80 + kk * 32 + ((lane >> 4) << 4);
                ldsm_x4(ah[mt], base + abyte);
                ldsm_x4(al[mt], base + 10240 + abyte);
            }
            #pragma unroll
            for (int bp = 0; bp < 4; bp++) {
                uint32_t brow = (uint32_t)(wn * 64 + bp * 16 + (lane & 7) + (((lane >> 4) & 1) << 3));
                uint32_t bbyte = brow * 80 + kk * 32 + (((lane >> 3) & 1) << 4);
                uint32_t bh4[4], bl4[4];
                ldsm_x4(bh4, base + 20480 + bbyte);
                ldsm_x4(bl4, base + 30720 + bbyte);
                #pragma unroll
                for (int sub = 0; sub < 2; sub++)
                    #pragma unroll
                    for (int mt = 0; mt < 2; mt++)
                        mma_bf16(acc[mt][bp * 2 + sub], ah[mt], bh4 + sub * 2);
                #pragma unroll
                for (int sub = 0; sub < 2; sub++)
                    #pragma unroll
                    for (int mt = 0; mt < 2; mt++)
                        mma_bf16(acc[mt][bp * 2 + sub], ah[mt], bl4 + sub * 2);
                #pragma unroll
                for (int sub = 0; sub < 2; sub++)
                    #pragma unroll
                    for (int mt = 0; mt < 2; mt++)
                        mma_bf16(acc[mt][bp * 2 + sub], al[mt], bh4 + sub * 2);
            }
        }
        __syncthreads();
    }

    if (ggh) {
        #pragma unroll
        for (int mt = 0; mt < 2; mt++) {
            int r0 = m0 + wm * 32 + mt * 16 + (lane >> 2);
            #pragma unroll
            for (int nt = 0; nt < 8; nt++) {
                int cc = n0 + wn * 64 + nt * 8 + (lane & 3) * 2;
                int gcol = cc >> 1;
                float ba = bias[gcol], bg = bias[gcol + FFD];
                #pragma unroll
                for (int h = 0; h < 2; h++) {
                    int r = r0 + h * 8;
                    if (r >= M) continue;
                    float a  = acc[mt][nt][h * 2]     + ba;
                    float gt = acc[mt][nt][h * 2 + 1] + bg;
                    float gl = 0.5f * gt * (1.f + erff(gt * 0.70710678118654752440f));
                    split_store(ggh, ggl, (size_t)r * FFD + gcol, a * gl);
                }
            }
        }
        return;
    }

    float mn = INFINITY, mx = -INFINITY;
    #pragma unroll
    for (int mt = 0; mt < 2; mt++) {
        int r0 = m0 + wm * 32 + mt * 16 + (lane >> 2);
        #pragma unroll
        for (int nt = 0; nt < 8; nt++) {
            int cc = n0 + wn * 64 + nt * 8 + (lane & 3) * 2;
            #pragma unroll
            for (int h = 0; h < 2; h++) {
                int r = r0 + h * 8;
                if (r >= M) continue;
                float2 o = make_float2(acc[mt][nt][h * 2], acc[mt][nt][h * 2 + 1]);
                if (bias) {
                    float2 bb = *(const float2*)(bias + cc);
                    o.x += bb.x; o.y += bb.y;
                }
                if (res) {
                    float2 rv = *(const float2*)(res + (size_t)r * N + cc);
                    o.x += rv.x; o.y += rv.y;
                }
                mn = fminf(mn, fminf(o.x, o.y));
                mx = fmaxf(mx, fmaxf(o.x, o.y));
                *(float2*)(C + (size_t)r * N + cc) = o;
            }
        }
    }

    if (slot >= 0) {
        for (int o = 16; o; o >>= 1) {
            mn = fminf(mn, __shfl_xor_sync(0xffffffffu, mn, o));
            mx = fmaxf(mx, __shfl_xor_sync(0xffffffffu, mx, o));
        }
        if (lane == 0) { rmn[wid] = mn; rmx[wid] = mx; }
        __syncthreads();
        if (tid == 0) {
            #pragma unroll
            for (int i = 1; i < 8; i++) { mn = fminf(mn, rmn[i]); mx = fmaxf(mx, rmx[i]); }
            mn = fminf(mn, rmn[0]); mx = fmaxf(mx, rmx[0]);
            atomicMinF(&g_stats[2 * slot], mn);
            atomicMaxF(&g_stats[2 * slot + 1], mx);
        }
    }
}

// ----------------------- stats init -----------------------------------------
__global__ void init_stats_kernel() {
    int t = threadIdx.x;
    if (t < 3) { g_stats[2 * t] = INFINITY; g_stats[2 * t + 1] = -INFINITY; }
    if (t == 3) g_stats[6] = 0.f;
}

// ----------------------- quantize Q+K in one launch (z-indexed) -------------
__global__ __launch_bounds__(256) void quant_qk2_kernel(
    const float* __restrict__ x0, int LDC0, int colofs0,
    __nv_bfloat16* __restrict__ out0, int S0, int SPAD0, int slot0,
    const float* __restrict__ x1, int LDC1, int colofs1,
    __nv_bfloat16* __restrict__ out1, int S1, int SPAD1, int slot1)
{
    const float* x; int LDC, colofs, S, SPAD, slot; __nv_bfloat16* out;
    if (blockIdx.z == 0) { x = x0; LDC = LDC0; colofs = colofs0; out = out0; S = S0; SPAD = SPAD0; slot = slot0; }
    else                 { x = x1; LDC = LDC1; colofs = colofs1; out = out1; S = S1; SPAD = SPAD1; slot = slot1; }
    int bh = blockIdx.y, s0 = blockIdx.x * 32;
    if (s0 >= SPAD) return;
    int b = bh >> 4, h = bh & 15;
    float mn = g_stats[2 * slot], mx = g_stats[2 * slot + 1];
    float delta = (mx - mn) * (1.f / 255.f);
    float zp = rintf(-mn / delta);
    #pragma unroll
    for (int it = 0; it < 10; it++) {
        int local = threadIdx.x + it * 256;
        int sl = local / 80, d = local % 80;
        int s = s0 + sl;
        float val = 0.f;
        if (d < 72 && s < S) {
            float xv = x[((size_t)b * S + s) * LDC + colofs + h * HDIM + d];
            float q = fminf(fmaxf(rintf(xv / delta) + zp, 0.f), 255.f);
            val = q - zp;
        }
        out[((size_t)bh * SPAD + s) * 80 + d] = __float2bfloat16(val);
    }
}

// V: coalesced via 32x32 smem tile transpose.
__global__ __launch_bounds__(256) void quant_v_kernel(
    const float* __restrict__ x, int LDC, int colofs,
    __nv_bfloat16* __restrict__ out, int S, int SPAD, int slot)
{
    __shared__ float tile[32][33];
    int bh = blockIdx.y, s0 = blockIdx.x * 32;
    int b = bh >> 4, h = bh & 15;
    float mn = g_stats[2 * slot], mx = g_stats[2 * slot + 1];
    float delta = (mx - mn) * (1.f / 255.f);
    float zp = rintf(-mn / delta);
    int tx = threadIdx.x & 31, ty = threadIdx.x >> 5;

    for (int dc0 = 0; dc0 < 128; dc0 += 32) {
        #pragma unroll
        for (int r = ty; r < 32; r += 8) {
            int s = s0 + r, d = dc0 + tx;
            float val = 0.f;
            if (d < 72 && s < S) {
                float xv = x[((size_t)b * S + s) * LDC + colofs + h * HDIM + d];
                float q = fminf(fmaxf(rintf(xv / delta) + zp, 0.f), 255.f);
                val = q - zp;
            }
            tile[r][tx] = val;
        }
        __syncthreads();
        #pragma unroll
        for (int r = ty; r < 32; r += 8) {
            int d = dc0 + r;
            out[((size_t)bh * 128 + d) * SPAD + s0 + tx] = __float2bfloat16(tile[tx][r]);
        }
        __syncthreads();
    }
}

// ----------------------- pass 1: stats only (no score store) ----------------
__global__ __launch_bounds__(256) void stats_mma_kernel(int SK, int KROWS, float premul)
{
    __shared__ char sA[128 * 176];
    __shared__ char sB[128 * 176];
    int tid = threadIdx.x, wid = tid >> 5, lane = tid & 31;
    int bh = blockIdx.z;
    int kcol0 = blockIdx.x * 128, qrow0 = blockIdx.y * 128;
    int wm = wid & 3, wn = wid >> 2;
    uint32_t sa = smem_to_u32(sA), sb = smem_to_u32(sB);

    const __nv_bfloat16* qb = g_qi + ((size_t)bh * 1024 + qrow0) * 80;
    const __nv_bfloat16* kb = g_ki + ((size_t)bh * KROWS + kcol0) * 80;
    #pragma unroll
    for (int i = 0; i < 5; i++) {
        int c = tid + i * 256;
        int row = c / 10, j = c - row * 10;
        cp16(sa + row * 176 + j * 16, qb + (size_t)row * 80 + j * 8, 16u);
        cp16(sb + row * 176 + j * 16, kb + (size_t)row * 80 + j * 8, 16u);
    }
    asm volatile("cp.async.commit_group;" ::: "memory");
    cpasync_wait<0>();
    __syncthreads();

    float acc[2][8][4];
    #pragma unroll
    for (int mt = 0; mt < 2; mt++)
        #pragma unroll
        for (int nt = 0; nt < 8; nt++)
            #pragma unroll
            for (int e = 0; e < 4; e++) acc[mt][nt][e] = 0.f;

    #pragma unroll
    for (int kk = 0; kk < 5; kk++) {
        uint32_t af[2][4];
        #pragma unroll
        for (int mt = 0; mt < 2; mt++) {
            uint32_t arow = (uint32_t)(wm * 32 + mt * 16 + (lane & 15));
            ldsm_x4(af[mt], sa + arow * 176 + kk * 32 + ((lane >> 4) << 4));
        }
        #pragma unroll
        for (int bp = 0; bp < 4; bp++) {
            uint32_t brow = (uint32_t)(wn * 64 + bp * 16 + (lane & 7) + (((lane >> 4) & 1) << 3));
            uint32_t bf4[4];
            ldsm_x4(bf4, sb + brow * 176 + kk * 32 + (((lane >> 3) & 1) << 4));
            #pragma unroll
            for (int sub = 0; sub < 2; sub++) {
                int nt = bp * 2 + sub;
                #pragma unroll
                for (int mt = 0; mt < 2; mt++)
                    mma_bf16(acc[mt][nt], af[mt], bf4 + sub * 2);
            }
        }
    }

    float dq = (g_stats[1] - g_stats[0]) * (1.f / 255.f);
    float dk = (g_stats[3] - g_stats[2]) * (1.f / 255.f);
    float sc = dq * dk * premul;

    #pragma unroll
    for (int mt = 0; mt < 2; mt++) {
        #pragma unroll
        for (int h2 = 0; h2 < 2; h2++) {
            int r = qrow0 + wm * 32 + mt * 16 + (lane >> 2) + h2 * 8;
            float zs = 0.f, mxv = -INFINITY;
            #pragma unroll
            for (int nt = 0; nt < 8; nt++) {
                int c0 = kcol0 + wn * 64 + nt * 8 + (lane & 3) * 2;
                float v0 = acc[mt][nt][h2 * 2]     * sc;
                float v1 = acc[mt][nt][h2 * 2 + 1] * sc;
                if (c0 < SK)     { zs += fexp(v0); mxv = fmaxf(mxv, v0); }
                if (c0 + 1 < SK) { zs += fexp(v1); mxv = fmaxf(mxv, v1); }
            }
            #pragma unroll
            for (int o = 1; o <= 2; o <<= 1) {
                zs  += __shfl_xor_sync(0xffffffffu, zs, o);
                mxv = fmaxf(mxv, __shfl_xor_sync(0xffffffffu, mxv, o));
            }
            if ((lane & 3) == 0) {
                size_t prow = ((size_t)bh * SEQ + r) * 16 + blockIdx.x * 2 + wn;
                g_partZ[prow] = zs;
                g_partM[prow] = mxv;
            }
        }
    }
}

// ----------------------- row reduce: Z, pmax (deterministic) ----------------
__global__ __launch_bounds__(256) void rowreduce_kernel(int nparts) {
    int row = blockIdx.x * 256 + threadIdx.x;
    if (row >= NROWSBH) return;
    float Z = 0.f, M = -INFINITY;
    const float* pz = g_partZ + (size_t)row * 16;
    const float* pm = g_partM + (size_t)row * 16;
    for (int j = 0; j < nparts; j++) { Z += pz[j]; M = fmaxf(M, pm[j]); }
    g_rowZ[row] = Z;
    float pr = fexp(M) / Z;
    for (int o = 16; o; o >>= 1) pr = fmaxf(pr, __shfl_xor_sync(0xffffffffu, pr, o));
    __shared__ float sh[8];
    if ((threadIdx.x & 31) == 0) sh[threadIdx.x >> 5] = pr;
    __syncthreads();
    if (threadIdx.x == 0) {
        for (int i = 1; i < 8; i++) pr = fmaxf(pr, sh[i]);
        atomicMaxF(&g_stats[6], pr);
    }
}

// ----------------------- pass 2: fused flash-style attention ----------------
#define PV2_Q   0
#define PV2_K   22528
#define PV2_V   45056
#define PV2_P   81920
#define PV2_SC  100352
#define PV2_SMEM 100864

__global__ __launch_bounds__(256, 2) void pv2_kernel(
    __nv_bfloat16* __restrict__ oh, __nv_bfloat16* __restrict__ ol,
    int SK, int SKPAD, float premul)
{
    extern __shared__ char smem[];
    uint32_t sb = smem_to_u32(smem);
    float* sscale = (float*)(smem + PV2_SC);
    int tid = threadIdx.x, wid = tid >> 5, lane = tid & 31;
    int bh = blockIdx.y, m0 = blockIdx.x * 128;
    int b = bh >> 4, h = bh & 15;
    int wm = wid & 3, wn = wid >> 2;
    size_t rowbase = (size_t)bh * SEQ + m0;

    const __nv_bfloat16* qb = g_qi + ((size_t)bh * SEQ + m0) * 80;
    const __nv_bfloat16* kb = g_ki + (size_t)bh * SKPAD * 80;
    const __nv_bfloat16* vb = g_vi + (size_t)bh * 128 * SKPAD;
    const int KT = SKPAD >> 6;

    float pmax = g_stats[6];
    if (tid < 128)
        sscale[tid] = 255.f / (g_rowZ[rowbase + tid] * pmax);

    float dq = (g_stats[1] - g_stats[0]) * (1.f / 255.f);
    float dk = (g_stats[3] - g_stats[2]) * (1.f / 255.f);
    float sc = dq * dk * premul;

    #pragma unroll
    for (int i = 0; i < 5; i++) {
        int c = tid + i * 256;
        int row = c / 10, j = c - row * 10;
        cp16(sb + PV2_Q + row * 176 + j * 16, qb + (size_t)row * 80 + j * 8, 16u);
    }
    #pragma unroll
    for (int i = 0; i < 3; i++) {
        int c = tid + i * 256;
        if (c < 640) {
            int row = c / 10, j = c - row * 10;
            cp16(sb + PV2_K + row * 176 + j * 16, kb + (size_t)row * 80 + j * 8, 16u);
        }
    }
    #pragma unroll
    for (int i = 0; i < 4; i++) {
        int c = tid + i * 256;
        int row = c >> 3, j = c & 7;
        cp16(sb + PV2_V + row * 144 + j * 16, vb + (size_t)row * SKPAD + j * 8, 16u);
    }
    asm volatile("cp.async.commit_group;" ::: "memory");

    float acc_o[2][8][4];
    #pragma unroll
    for (int mt = 0; mt < 2; mt++)
        #pragma unroll
        for (int nt = 0; nt < 8; nt++)
            #pragma unroll
            for (int e = 0; e < 4; e++) acc_o[mt][nt][e] = 0.f;

    for (int t = 0; t < KT; t++) {
        if (t + 1 < KT) {
            uint32_t kbuf = sb + PV2_K + ((t + 1) & 1) * 11264;
            uint32_t vbuf = sb + PV2_V + ((t + 1) & 1) * 18432;
            const __nv_bfloat16* kg = kb + (size_t)(t + 1) * 64 * 80;
            const __nv_bfloat16* vg = vb + (size_t)(t + 1) * 64;
            #pragma unroll
            for (int i = 0; i < 3; i++) {
                int c = tid + i * 256;
                if (c < 640) {
                    int row = c / 10, j = c - row * 10;
                    cp16(kbuf + row * 176 + j * 16, kg + (size_t)row * 80 + j * 8, 16u);
                }
            }
            #pragma unroll
            for (int i = 0; i < 4; i++) {
                int c = tid + i * 256;
                int row = c >> 3, j = c & 7;
                cp16(vbuf + row * 144 + j * 16, vg + (size_t)row * SKPAD + j * 8, 16u);
            }
            asm volatile("cp.async.commit_group;" ::: "memory");
            cpasync_wait<1>();
        } else {
            cpasync_wait<0>();
        }
        __syncthreads();   // K/V(t) ready

        uint32_t kbase = sb + PV2_K + (t & 1) * 11264;
        uint32_t vbase = sb + PV2_V + (t & 1) * 18432;

        float acc_s[2][4][4];
        #pragma unroll
        for (int mt = 0; mt < 2; mt++)
            #pragma unroll
            for (int nt = 0; nt < 4; nt++)
                #pragma unroll
                for (int e = 0; e < 4; e++) acc_s[mt][nt][e] = 0.f;

        #pragma unroll
        for (int kk = 0; kk < 5; kk++) {
            uint32_t af[2][4];
            #pragma unroll
            for (int mt = 0; mt < 2; mt++) {
                uint32_t arow = (uint32_t)(wm * 32 + mt * 16 + (lane & 15));
                ldsm_x4(af[mt], sb + PV2_Q + arow * 176 + kk * 32 + ((lane >> 4) << 4));
            }
            #pragma unroll
            for (int bp = 0; bp < 2; bp++) {
                uint32_t brow = (uint32_t)(wn * 32 + bp * 16 + (lane & 7) + (((lane >> 4) & 1) << 3));
                uint32_t bf4[4];
                ldsm_x4(bf4, kbase + brow * 176 + kk * 32 + (((lane >> 3) & 1) << 4));
                #pragma unroll
                for (int sub = 0; sub < 2; sub++) {
                    int nt = bp * 2 + sub;
                    #pragma unroll
                    for (int mt = 0; mt < 2; mt++)
                        mma_bf16(acc_s[mt][nt], af[mt], bf4 + sub * 2);
                }
            }
        }

        #pragma unroll
        for (int mt = 0; mt < 2; mt++) {
            #pragma unroll
            for (int h2 = 0; h2 < 2; h2++) {
                int rl = wm * 32 + mt * 16 + (lane >> 2) + h2 * 8;
                float rsc = sscale[rl];
                #pragma unroll
                for (int nt = 0; nt < 4; nt++) {
                    int kcl = wn * 32 + nt * 8 + (lane & 3) * 2;
                    int kcg = t * 64 + kcl;
                    float p0 = 0.f, p1 = 0.f;
                    if (kcg < SK)
                        p0 = fminf(rintf(fexp(acc_s[mt][nt][h2 * 2] * sc) * rsc), 255.f);
                    if (kcg + 1 < SK)
                        p1 = fminf(rintf(fexp(acc_s[mt][nt][h2 * 2 + 1] * sc) * rsc), 255.f);
                    *(__nv_bfloat162*)(smem + PV2_P + rl * 144 + kcl * 2) =
                        __nv_bfloat162(__float2bfloat16(p0), __float2bfloat16(p1));
                }
            }
        }
        __syncthreads();   // P complete

        #pragma unroll
        for (int kk = 0; kk < 4; kk++) {
            uint32_t af[2][4];
            #pragma unroll
            for (int mt = 0; mt < 2; mt++) {
                uint32_t arow = (uint32_t)(wm * 32 + mt * 16 + (lane & 15));
                ldsm_x4(af[mt], sb + PV2_P + arow * 144 + kk * 32 + ((lane >> 4) << 4));
            }
            int bplim = (wn == 0) ? 4 : 1;
            for (int bp = 0; bp < bplim; bp++) {
                uint32_t brow = (uint32_t)(wn * 64 + bp * 16 + (lane & 7) + (((lane >> 4) & 1) << 3));
                uint32_t bf4[4];
                ldsm_x4(bf4, vbase + brow * 144 + kk * 32 + (((lane >> 3) & 1) << 4));
                #pragma unroll
                for (int sub = 0; sub < 2; sub++) {
                    int nt = bp * 2 + sub;
                    #pragma unroll
                    for (int mt = 0; mt < 2; mt++)
                        mma_bf16(acc_o[mt][nt], af[mt], bf4 + sub * 2);
                }
            }
        }
        __syncthreads();   // drain readers of K/V(t) before its buffer is reused
    }

    float dp = pmax * (1.f / 255.f);
    float dv = (g_stats[5] - g_stats[4]) * (1.f / 255.f);
    float osc = dp * dv;

    #pragma unroll
    for (int mt = 0; mt < 2; mt++) {
        int r0 = m0 + wm * 32 + mt * 16 + (lane >> 2);
        #pragma unroll
        for (int nt = 0; nt < 8; nt++) {
            int n = wn * 64 + nt * 8 + (lane & 3) * 2;
            if (n >= 72) continue;
            #pragma unroll
            for (int h2 = 0; h2 < 2; h2++) {
                int r = r0 + h2 * 8;
                size_t idx = ((size_t)b * SEQ + r) * DMODEL + h * HDIM + n;
                split_store(oh, ol, idx,     acc_o[mt][nt][h2 * 2]     * osc);
                split_store(oh, ol, idx + 1, acc_o[mt][nt][h2 * 2 + 1] * osc);
            }
        }
    }
}

// ----------------------- host orchestration ---------------------------------
static void tc_gemm(const __nv_bfloat16* ah, const __nv_bfloat16* al,
                    const __nv_bfloat16* bh, const __nv_bfloat16* bl,
                    const float* bias, const float* res,
                    float* C, int M, int N, int K, int slot = -1,
                    __nv_bfloat16* ggh = nullptr, __nv_bfloat16* ggl = nullptr) {
    static bool attr_set = false;
    if (!attr_set) {
        cudaFuncSetAttribute(tc_gemm_kernel, cudaFuncAttributeMaxDynamicSharedMemorySize,
                             TC_SMEM_TOTAL);
        cudaFuncSetAttribute(pv2_kernel, cudaFuncAttributeMaxDynamicSharedMemorySize,
                             PV2_SMEM);
        attr_set = true;
    }
    dim3 grid(N / 128, (M + 127) / 128);
    tc_gemm_kernel<<<grid, 256, TC_SMEM_TOTAL>>>(ah, al, bh, bl,
                                                 bias, res, C, M, N, K, slot, ggh, ggl);
}

extern "C" void kernel_launch(void* const* d_in, const int* in_sizes, int n_in,
                              void* d_out, int out_size) {
    (void)in_sizes; (void)n_in; (void)out_size;
    const float* hs    = (const float*)d_in[0];
    const float* enc   = (const float*)d_in[1];
    const float* ln1g  = (const float*)d_in[2];
    const float* ln1b  = (const float*)d_in[3];
    const float* Wq1   = (const float*)d_in[4];
    const float* Wk1   = (const float*)d_in[5];
    const float* Wv1   = (const float*)d_in[6];
    const float* Wo1   = (const float*)d_in[7];
    const float* bo1   = (const float*)d_in[8];
    const float* ln2g  = (const float*)d_in[9];
    const float* ln2b  = (const float*)d_in[10];
    const float* Wq2   = (const float*)d_in[11];
    const float* Wk2   = (const float*)d_in[12];
    const float* Wv2   = (const float*)d_in[13];
    const float* Wo2   = (const float*)d_in[14];
    const float* bo2   = (const float*)d_in[15];
    const float* ln3g  = (const float*)d_in[16];
    const float* ln3b  = (const float*)d_in[17];
    const float* Wff1  = (const float*)d_in[18];
    const float* bff1  = (const float*)d_in[19];
    const float* Wff2  = (const float*)d_in[20];
    const float* bff2  = (const float*)d_in[21];
    float* out = (float*)d_out;

    void* p;
    cudaGetSymbolAddress(&p, g_q);      float* q_  = (float*)p;
    cudaGetSymbolAddress(&p, g_proj);   float* pj_ = (float*)p;
    __nv_bfloat16 *ah_, *al_, *gh_, *gl_, *bh_, *bl_;
    cudaGetSymbolAddress(&p, g_ah);   ah_ = (__nv_bfloat16*)p;
    cudaGetSymbolAddress(&p, g_al);   al_ = (__nv_bfloat16*)p;
    cudaGetSymbolAddress(&p, g_gh);   gh_ = (__nv_bfloat16*)p;
    cudaGetSymbolAddress(&p, g_gl);   gl_ = (__nv_bfloat16*)p;
    cudaGetSymbolAddress(&p, g_bh);   bh_ = (__nv_bfloat16*)p;
    cudaGetSymbolAddress(&p, g_bl);   bl_ = (__nv_bfloat16*)p;
    __nv_bfloat16 *qi_, *ki_, *vi_;
    cudaGetSymbolAddress(&p, g_qi);   qi_ = (__nv_bfloat16*)p;
    cudaGetSymbolAddress(&p, g_ki);   ki_ = (__nv_bfloat16*)p;
    cudaGetSymbolAddress(&p, g_vi);   vi_ = (__nv_bfloat16*)p;

    const float premul = 1.0f / sqrtf((float)HDIM);
    const size_t nE = (size_t)ENCROWS * DMODEL;
    const size_t WSTRIDE = (size_t)DMODEL * DMODEL;

    // ================= self-attention (fused QKV GEMM) =================
    init_stats_kernel<<<1, 32>>>();
    ln_split_kernel<<<ROWS, 256>>>(hs, ln1g, ln1b, ah_, al_);
    // QKV transposes in one launch (z = 0,1,2)
    wt_trans_split_kernel<<<dim3(36, 36, 3), 256>>>(
        Wq1, Wk1, Wv1, DMODEL, DMODEL, 0, 0, 1, 0, bh_, bl_, WSTRIDE);
    tc_gemm(ah_, al_, bh_, bl_, nullptr, nullptr, pj_, ROWS, 3456, DMODEL, 0);
    quant_qk2_kernel<<<dim3(32, BH, 2), 256>>>(
        pj_, 3456, 0,    qi_, SEQ, 1024, 0,
        pj_, 3456, 1152, ki_, SEQ, 1024, 1);
    quant_v_kernel<<<dim3(32, BH), 256>>>(pj_, 3456, 2304, vi_, SEQ, 1024, 2);
    stats_mma_kernel<<<dim3(8, 8, BH), 256>>>(SEQ, 1024, premul);
    rowreduce_kernel<<<NROWSBH / 256, 256>>>(16);
    pv2_kernel<<<dim3(8, BH), 256, PV2_SMEM>>>(ah_, al_, SEQ, 1024, premul);
    wt_trans_split_kernel<<<dim3(36, 36, 1), 256>>>(
        Wo1, Wo1, Wo1, DMODEL, DMODEL, 0, 0, 1, 0, bh_, bl_, 0);
    tc_gemm(ah_, al_, bh_, bl_, bo1, hs, out, ROWS, DMODEL, DMODEL);

    // ================= cross-attention (fused KV GEMM) =================
    init_stats_kernel<<<1, 32>>>();
    ln_split_kernel<<<ROWS, 256>>>(out, ln2g, ln2b, ah_, al_);
    wt_trans_split_kernel<<<dim3(36, 36, 1), 256>>>(
        Wq2, Wq2, Wq2, DMODEL, DMODEL, 0, 0, 1, 0, bh_, bl_, 0);
    tc_gemm(ah_, al_, bh_, bl_, nullptr, nullptr, q_, ROWS, DMODEL, DMODEL, 0);
    convert_split_kernel<<<2048, 256>>>(enc, nE / 4, ah_, al_);
    wt_trans_split_kernel<<<dim3(36, 36, 2), 256>>>(
        Wk2, Wv2, Wv2, DMODEL, DMODEL, 0, 0, 1, 0, bh_, bl_, WSTRIDE);
    tc_gemm(ah_, al_, bh_, bl_, nullptr, nullptr, pj_, ENCROWS, 2304, DMODEL, 1);
    quant_qk2_kernel<<<dim3(32, BH, 2), 256>>>(
        q_,  1152, 0, qi_, SEQ,  1024, 0,
        pj_, 2304, 0, ki_, SENC, 128,  1);
    quant_v_kernel<<<dim3(4, BH), 256>>>(pj_, 2304, 1152, vi_, SENC, 128, 2);
    stats_mma_kernel<<<dim3(1, 8, BH), 256>>>(SENC, 128, premul);
    rowreduce_kernel<<<NROWSBH / 256, 256>>>(2);
    pv2_kernel<<<dim3(8, BH), 256, PV2_SMEM>>>(ah_, al_, SENC, 128, premul);
    wt_trans_split_kernel<<<dim3(36, 36, 1), 256>>>(
        Wo2, Wo2, Wo2, DMODEL, DMODEL, 0, 0, 1, 0, bh_, bl_, 0);
    tc_gemm(ah_, al_, bh_, bl_, bo2, out, out, ROWS, DMODEL, DMODEL);

    // ================= feed-forward (GEGLU fused into FF1 epilogue) =========
    ln_split_kernel<<<ROWS, 256>>>(out, ln3g, ln3b, ah_, al_);
    // interleaved FF1 transpose, both halves in one launch:
    // z=0: a-cols -> rows 2c; z=1: gate-cols (src0+FFD) -> rows 2c+1
    wt_trans_split_kernel<<<dim3(FFD / 32, DMODEL / 32, 2), 256>>>(
        Wff1, Wff1, Wff1, DMODEL, 2 * FFD, 0, FFD, 2, 1, bh_, bl_, 0);
    tc_gemm(ah_, al_, bh_, bl_, bff1, nullptr, nullptr, ROWS, 2 * FFD, DMODEL, -1,
            gh_, gl_);
    wt_trans_split_kernel<<<dim3(36, FFD / 32, 1), 256>>>(
        Wff2, Wff2, Wff2, FFD, DMODEL, 0, 0, 1, 0, bh_, bl_, 0);
    tc_gemm(gh_, gl_, bh_, bl_, bff2, out, out, ROWS, DMODEL, FFD);
}

// round 17
// speedup vs baseline: 1.2510x; 1.2355x over previous
#include <cuda_runtime.h>
#include <cuda_bf16.h>
#include <cuda_fp16.h>
#include <math.h>
#include <stdint.h>

// Problem dims
#define BATCH   8
#define SEQ     1024
#define DMODEL  1152
#define NHEAD   16
#define HDIM    72
#define SENC    77
#define FFD     4608
#define ROWS    (BATCH*SEQ)        // 8192
#define ENCROWS (BATCH*SENC)       // 616
#define BH      (BATCH*NHEAD)      // 128
#define NROWSBH (BH*SEQ)           // 131072

__device__ __forceinline__ uint32_t smem_to_u32(const void* smem_ptr) {
    uint32_t addr;
    asm("{ .reg .u64 tmp; cvta.to.shared.u64 tmp, %1; cvt.u32.u64 %0, tmp; }"
        : "=r"(addr) : "l"(smem_ptr));
    return addr;
}

// fast exp on the FMA pipe (no MUFU). rel err ~2e-7.
__device__ __forceinline__ float fexp(float x) {
    float t = x * 1.4426950408889634f;
    t = fmaxf(t, -126.0f);
    float fi = floorf(t);
    float f = t - fi;
    float p = 1.3333558146e-3f;
    p = fmaf(p, f, 9.6181291076e-3f);
    p = fmaf(p, f, 5.5504108664e-2f);
    p = fmaf(p, f, 2.4022650695910e-1f);
    p = fmaf(p, f, 6.9314718055994e-1f);
    p = fmaf(p, f, 1.0f);
    return p * __int_as_float(((int)fi + 127) << 23);
}

// bf16 hi/lo split store
__device__ __forceinline__ void split_store(
    __nv_bfloat16* __restrict__ h, __nv_bfloat16* __restrict__ l,
    size_t idx, float v)
{
    __nv_bfloat16 hh = __float2bfloat16(v);
    h[idx] = hh;
    l[idx] = __float2bfloat16(v - __bfloat162float(hh));
}
// fp16 hi/lo split store (into the same 16-bit buffers)
__device__ __forceinline__ void split_store_h(
    __nv_bfloat16* __restrict__ h, __nv_bfloat16* __restrict__ l,
    size_t idx, float v)
{
    __half hh = __float2half(v);
    reinterpret_cast<__half*>(h)[idx] = hh;
    reinterpret_cast<__half*>(l)[idx] = __float2half(v - __half2float(hh));
}

// ----------------------- scratch (device globals; no runtime alloc) ---------
__device__ float g_q[(size_t)ROWS*DMODEL];
__device__ float g_rowZ[NROWSBH];
__device__ float g_partZ[(size_t)NROWSBH*16];
__device__ float g_partM[(size_t)NROWSBH*16];
__device__ float g_proj[(size_t)ROWS*3456];          // fused QKV / KV outputs
__device__ float g_stats[8];
// 16-bit hi/lo operand buffers (bf16 or fp16 depending on GEMM mode)
__device__ __nv_bfloat16 g_ah[(size_t)ROWS*DMODEL];
__device__ __nv_bfloat16 g_al[(size_t)ROWS*DMODEL];
__device__ __nv_bfloat16 g_gh[(size_t)ROWS*FFD];     // geglu output (FF2 A operand)
__device__ __nv_bfloat16 g_gl[(size_t)ROWS*FFD];
__device__ __nv_bfloat16 g_bh[(size_t)(2*FFD)*DMODEL];
__device__ __nv_bfloat16 g_bl[(size_t)(2*FFD)*DMODEL];
// integer-bf16 attention operands
__device__ __nv_bfloat16 g_qi[(size_t)BH*1024*80];
__device__ __nv_bfloat16 g_ki[(size_t)BH*1024*80];
__device__ __nv_bfloat16 g_vi[(size_t)BH*128*1024];

// ----------------------- atomic float min/max -------------------------------
__device__ __forceinline__ void atomicMaxF(float* a, float v) {
    if (v >= 0.f) atomicMax((int*)a, __float_as_int(v));
    else          atomicMin((unsigned int*)a, __float_as_uint(v));
}
__device__ __forceinline__ void atomicMinF(float* a, float v) {
    if (v >= 0.f) atomicMin((int*)a, __float_as_int(v));
    else          atomicMax((unsigned int*)a, __float_as_uint(v));
}

// ----------------------- LayerNorm -> 16-bit hi/lo ---------------------------
__global__ __launch_bounds__(256) void ln_split_kernel(
    const float* __restrict__ x, const float* __restrict__ g,
    const float* __restrict__ b,
    __nv_bfloat16* __restrict__ oh, __nv_bfloat16* __restrict__ ol, int prec)
{
    const int N = DMODEL;
    size_t row = blockIdx.x;
    const float* xr = x + row * N;
    int tid = threadIdx.x;

    float lv[5];
    int cnt = 0;
    float s = 0.f;
    for (int i = tid; i < N; i += 256) { float t = xr[i]; lv[cnt++] = t; s += t; }

    __shared__ float sh[8];
    for (int ofs = 16; ofs; ofs >>= 1) s += __shfl_xor_sync(0xffffffffu, s, ofs);
    if ((tid & 31) == 0) sh[tid >> 5] = s;
    __syncthreads();
    float tot = 0.f;
    #pragma unroll
    for (int i = 0; i < 8; i++) tot += sh[i];
    float mu = tot * (1.f / (float)N);

    float vs = 0.f;
    for (int c = 0; c < cnt; c++) { float d = lv[c] - mu; vs += d * d; }
    __syncthreads();
    for (int ofs = 16; ofs; ofs >>= 1) vs += __shfl_xor_sync(0xffffffffu, vs, ofs);
    if ((tid & 31) == 0) sh[tid >> 5] = vs;
    __syncthreads();
    float vtot = 0.f;
    #pragma unroll
    for (int i = 0; i < 8; i++) vtot += sh[i];
    float inv = rsqrtf(vtot * (1.f / (float)N) + 1e-5f);

    int i = tid;
    for (int c = 0; c < cnt; c++, i += 256) {
        float val = (lv[c] - mu) * inv * g[i] + b[i];
        if (prec == 0) split_store(oh, ol, row * N + i, val);
        else           split_store_h(oh, ol, row * N + i, val);
    }
}

// ----------------------- fp32 -> bf16 hi/lo split (for enc) -----------------
__global__ __launch_bounds__(256) void convert_split_kernel(
    const float* __restrict__ x, size_t n4,
    __nv_bfloat16* __restrict__ h, __nv_bfloat16* __restrict__ l)
{
    for (size_t i = (size_t)blockIdx.x * blockDim.x + threadIdx.x; i < n4;
         i += (size_t)gridDim.x * blockDim.x) {
        float4 v = ((const float4*)x)[i];
        __nv_bfloat16 h0 = __float2bfloat16(v.x);
        __nv_bfloat16 h1 = __float2bfloat16(v.y);
        __nv_bfloat16 h2 = __float2bfloat16(v.z);
        __nv_bfloat16 h3 = __float2bfloat16(v.w);
        __nv_bfloat162* hp = (__nv_bfloat162*)h;
        __nv_bfloat162* lp = (__nv_bfloat162*)l;
        hp[2*i]   = __nv_bfloat162(h0, h1);
        hp[2*i+1] = __nv_bfloat162(h2, h3);
        lp[2*i]   = __nv_bfloat162(__float2bfloat16(v.x - __bfloat162float(h0)),
                                   __float2bfloat16(v.y - __bfloat162float(h1)));
        lp[2*i+1] = __nv_bfloat162(__float2bfloat16(v.z - __bfloat162float(h2)),
                                   __float2bfloat16(v.w - __bfloat162float(h3)));
    }
}

// ----------------------- weight transpose + split (multi-z, prec) -----------
// prec 0: bf16 hi+lo.  prec 1: fp16 hi only (lo unused by fp16 GEMM).
__global__ __launch_bounds__(256) void wt_trans_split_kernel(
    const float* __restrict__ W0, const float* __restrict__ W1,
    const float* __restrict__ W2,
    int K, int N, int src0, int src_step, int out_mul, int out_add_step,
    __nv_bfloat16* __restrict__ Th, __nv_bfloat16* __restrict__ Tl,
    size_t outstride, int prec)
{
    __shared__ float tile[32][33];
    int z = blockIdx.z;
    const float* W = (z == 0) ? W0 : ((z == 1) ? W1 : W2);
    int src = src0 + z * src_step;
    int oadd = z * out_add_step;
    Th += (size_t)z * outstride;
    Tl += (size_t)z * outstride;
    int nloc0 = blockIdx.x * 32, k0 = blockIdx.y * 32;
    int tx = threadIdx.x & 31, ty = threadIdx.x >> 5;
    #pragma unroll
    for (int r = ty; r < 32; r += 8) {
        int k = k0 + r, n = src + nloc0 + tx;
        tile[r][tx] = (k < K && n < N) ? W[(size_t)k * N + n] : 0.f;
    }
    __syncthreads();
    #pragma unroll
    for (int r = ty; r < 32; r += 8) {
        int nloc = nloc0 + r, k = k0 + tx;
        if (k < K && (src + nloc) < N) {
            float x = tile[tx][r];
            int outn = out_mul * nloc + oadd;
            if (prec == 0) {
                __nv_bfloat16 hh = __float2bfloat16(x);
                Th[(size_t)outn * K + k] = hh;
                Tl[(size_t)outn * K + k] = __float2bfloat16(x - __bfloat162float(hh));
            } else {
                reinterpret_cast<__half*>(Th)[(size_t)outn * K + k] = __float2half(x);
            }
        }
    }
}

// ----------------------- mma primitives -------------------------------------
__device__ __forceinline__ void cp16(uint32_t dst, const void* src, uint32_t sz) {
    asm volatile("cp.async.cg.shared.global [%0], [%1], 16, %2;"
                 :: "r"(dst), "l"(src), "r"(sz) : "memory");
}
template<int NN> __device__ __forceinline__ void cpasync_wait() {
    asm volatile("cp.async.wait_group %0;" :: "n"(NN) : "memory");
}
__device__ __forceinline__ void ldsm_x4(uint32_t* r, uint32_t addr) {
    asm volatile("ldmatrix.sync.aligned.m8n8.x4.shared.b16 {%0,%1,%2,%3}, [%4];"
        : "=r"(r[0]), "=r"(r[1]), "=r"(r[2]), "=r"(r[3]) : "r"(addr));
}
__device__ __forceinline__ void mma_bf16(float* c, const uint32_t* a, const uint32_t* b) {
    asm volatile("mma.sync.aligned.m16n8k16.row.col.f32.bf16.bf16.f32 "
        "{%0,%1,%2,%3}, {%4,%5,%6,%7}, {%8,%9}, {%0,%1,%2,%3};"
        : "+f"(c[0]), "+f"(c[1]), "+f"(c[2]), "+f"(c[3])
        : "r"(a[0]), "r"(a[1]), "r"(a[2]), "r"(a[3]), "r"(b[0]), "r"(b[1]));
}
__device__ __forceinline__ void mma_f16(float* c, const uint32_t* a, const uint32_t* b) {
    asm volatile("mma.sync.aligned.m16n8k16.row.col.f32.f16.f16.f32 "
        "{%0,%1,%2,%3}, {%4,%5,%6,%7}, {%8,%9}, {%0,%1,%2,%3};"
        : "+f"(c[0]), "+f"(c[1]), "+f"(c[2]), "+f"(c[3])
        : "r"(a[0]), "r"(a[1]), "r"(a[2]), "r"(a[3]), "r"(b[0]), "r"(b[1]));
}

// ----------------------- GEMM (templated precision mode) --------------------
// MODE 0: bf16x3 (A hi/lo, B hi/lo; AhBh + AhBl + AlBh)
// MODE 1: fp16x2 (A hi/lo, B fp16 single; AhB + AlB) — Bl never loaded
#define TC_STAGE_BYTES 40960
#define TC_SMEM_TOTAL  (2*TC_STAGE_BYTES)

template<int MODE>
__device__ __forceinline__ void tc_load_stage(
    uint32_t sbase,
    const __nv_bfloat16* __restrict__ Ah, const __nv_bfloat16* __restrict__ Al,
    const __nv_bfloat16* __restrict__ Bh, const __nv_bfloat16* __restrict__ Bl,
    int m0, int M, int n0, int K, int k0, int tid)
{
    #pragma unroll
    for (int i = 0; i < 2; i++) {
        int c = tid + i * 256;
        int row = c >> 2, kc = c & 3;
        uint32_t soff = (uint32_t)(row * 80 + kc * 16);
        size_t goffA = (size_t)(m0 + row) * K + k0 + kc * 8;
        uint32_t szA = ((m0 + row) < M) ? 16u : 0u;
        cp16(sbase + soff,         Ah + goffA, szA);
        cp16(sbase + 10240 + soff, Al + goffA, szA);
        size_t goffB = (size_t)(n0 + row) * K + k0 + kc * 8;
        cp16(sbase + 20480 + soff, Bh + goffB, 16u);
        if (MODE == 0)
            cp16(sbase + 30720 + soff, Bl + goffB, 16u);
    }
    asm volatile("cp.async.commit_group;" ::: "memory");
}

// If ggh != nullptr: geglu epilogue (adjacent even/odd cols are (a, gate)).
template<int MODE>
__global__ __launch_bounds__(256, 2) void tc_gemm_kernel(
    const __nv_bfloat16* __restrict__ Ah, const __nv_bfloat16* __restrict__ Al,
    const __nv_bfloat16* __restrict__ Bh, const __nv_bfloat16* __restrict__ Bl,
    const float* __restrict__ bias, const float* __restrict__ res,
    float* __restrict__ C, int M, int N, int K, int slot,
    __nv_bfloat16* __restrict__ ggh, __nv_bfloat16* __restrict__ ggl)
{
    extern __shared__ char smem[];
    __shared__ float rmn[8], rmx[8];
    uint32_t sb = smem_to_u32(smem);
    int tid = threadIdx.x;
    int wid = tid >> 5, lane = tid & 31;
    int n0 = blockIdx.x * 128, m0 = blockIdx.y * 128;
    int wm = wid & 3, wn = wid >> 2;
    if (slot >= 0) slot += n0 / 1152;   // fused multi-tensor outputs

    float acc[2][8][4];
    #pragma unroll
    for (int mt = 0; mt < 2; mt++)
        #pragma unroll
        for (int nt = 0; nt < 8; nt++)
            #pragma unroll
            for (int e = 0; e < 4; e++) acc[mt][nt][e] = 0.f;

    const int KT = K >> 5;

    tc_load_stage<MODE>(sb, Ah, Al, Bh, Bl, m0, M, n0, K, 0, tid);

    for (int t = 0; t < KT; t++) {
        if (t + 1 < KT) {
            tc_load_stage<MODE>(sb + ((t + 1) & 1) * TC_STAGE_BYTES,
                                Ah, Al, Bh, Bl, m0, M, n0, K, (t + 1) << 5, tid);
            cpasync_wait<1>();
        } else {
            cpasync_wait<0>();
        }
        __syncthreads();

        uint32_t base = sb + (t & 1) * TC_STAGE_BYTES;
        #pragma unroll
        for (int kk = 0; kk < 2; kk++) {
            uint32_t ah[2][4], al[2][4];
            #pragma unroll
            for (int mt = 0; mt < 2; mt++) {
                uint32_t arow = (uint32_t)(wm * 32 + mt * 16 + (lane & 15));
                uint32_t abyte = arow * 80 + kk * 32 + ((lane >> 4) << 4);
                ldsm_x4(ah[mt], base + abyte);
                ldsm_x4(al[mt], base + 10240 + abyte);
            }
            #pragma unroll
            for (int bp = 0; bp < 4; bp++) {
                uint32_t brow = (uint32_t)(wn * 64 + bp * 16 + (lane & 7) + (((lane >> 4) & 1) << 3));
                uint32_t bbyte = brow * 80 + kk * 32 + (((lane >> 3) & 1) << 4);
                uint32_t bh4[4];
                ldsm_x4(bh4, base + 20480 + bbyte);
                if (MODE == 0) {
                    uint32_t bl4[4];
                    ldsm_x4(bl4, base + 30720 + bbyte);
                    #pragma unroll
                    for (int sub = 0; sub < 2; sub++)
                        #pragma unroll
                        for (int mt = 0; mt < 2; mt++)
                            mma_bf16(acc[mt][bp * 2 + sub], ah[mt], bh4 + sub * 2);
                    #pragma unroll
                    for (int sub = 0; sub < 2; sub++)
                        #pragma unroll
                        for (int mt = 0; mt < 2; mt++)
                            mma_bf16(acc[mt][bp * 2 + sub], ah[mt], bl4 + sub * 2);
                    #pragma unroll
                    for (int sub = 0; sub < 2; sub++)
                        #pragma unroll
                        for (int mt = 0; mt < 2; mt++)
                            mma_bf16(acc[mt][bp * 2 + sub], al[mt], bh4 + sub * 2);
                } else {
                    #pragma unroll
                    for (int sub = 0; sub < 2; sub++)
                        #pragma unroll
                        for (int mt = 0; mt < 2; mt++)
                            mma_f16(acc[mt][bp * 2 + sub], ah[mt], bh4 + sub * 2);
                    #pragma unroll
                    for (int sub = 0; sub < 2; sub++)
                        #pragma unroll
                        for (int mt = 0; mt < 2; mt++)
                            mma_f16(acc[mt][bp * 2 + sub], al[mt], bh4 + sub * 2);
                }
            }
        }
        __syncthreads();
    }

    if (ggh) {
        #pragma unroll
        for (int mt = 0; mt < 2; mt++) {
            int r0 = m0 + wm * 32 + mt * 16 + (lane >> 2);
            #pragma unroll
            for (int nt = 0; nt < 8; nt++) {
                int cc = n0 + wn * 64 + nt * 8 + (lane & 3) * 2;
                int gcol = cc >> 1;
                float ba = bias[gcol], bg = bias[gcol + FFD];
                #pragma unroll
                for (int h = 0; h < 2; h++) {
                    int r = r0 + h * 8;
                    if (r >= M) continue;
                    float a  = acc[mt][nt][h * 2]     + ba;
                    float gt = acc[mt][nt][h * 2 + 1] + bg;
                    float gl = 0.5f * gt * (1.f + erff(gt * 0.70710678118654752440f));
                    if (MODE == 1) split_store_h(ggh, ggl, (size_t)r * FFD + gcol, a * gl);
                    else           split_store(ggh, ggl, (size_t)r * FFD + gcol, a * gl);
                }
            }
        }
        return;
    }

    float mn = INFINITY, mx = -INFINITY;
    #pragma unroll
    for (int mt = 0; mt < 2; mt++) {
        int r0 = m0 + wm * 32 + mt * 16 + (lane >> 2);
        #pragma unroll
        for (int nt = 0; nt < 8; nt++) {
            int cc = n0 + wn * 64 + nt * 8 + (lane & 3) * 2;
            #pragma unroll
            for (int h = 0; h < 2; h++) {
                int r = r0 + h * 8;
                if (r >= M) continue;
                float2 o = make_float2(acc[mt][nt][h * 2], acc[mt][nt][h * 2 + 1]);
                if (bias) {
                    float2 bb = *(const float2*)(bias + cc);
                    o.x += bb.x; o.y += bb.y;
                }
                if (res) {
                    float2 rv = *(const float2*)(res + (size_t)r * N + cc);
                    o.x += rv.x; o.y += rv.y;
                }
                mn = fminf(mn, fminf(o.x, o.y));
                mx = fmaxf(mx, fmaxf(o.x, o.y));
                *(float2*)(C + (size_t)r * N + cc) = o;
            }
        }
    }

    if (slot >= 0) {
        for (int o = 16; o; o >>= 1) {
            mn = fminf(mn, __shfl_xor_sync(0xffffffffu, mn, o));
            mx = fmaxf(mx, __shfl_xor_sync(0xffffffffu, mx, o));
        }
        if (lane == 0) { rmn[wid] = mn; rmx[wid] = mx; }
        __syncthreads();
        if (tid == 0) {
            #pragma unroll
            for (int i = 1; i < 8; i++) { mn = fminf(mn, rmn[i]); mx = fmaxf(mx, rmx[i]); }
            mn = fminf(mn, rmn[0]); mx = fmaxf(mx, rmx[0]);
            atomicMinF(&g_stats[2 * slot], mn);
            atomicMaxF(&g_stats[2 * slot + 1], mx);
        }
    }
}

// ----------------------- stats init -----------------------------------------
__global__ void init_stats_kernel() {
    int t = threadIdx.x;
    if (t < 3) { g_stats[2 * t] = INFINITY; g_stats[2 * t + 1] = -INFINITY; }
    if (t == 3) g_stats[6] = 0.f;
}

// ----------------------- quantize Q+K in one launch (z-indexed) -------------
__global__ __launch_bounds__(256) void quant_qk2_kernel(
    const float* __restrict__ x0, int LDC0, int colofs0,
    __nv_bfloat16* __restrict__ out0, int S0, int SPAD0, int slot0,
    const float* __restrict__ x1, int LDC1, int colofs1,
    __nv_bfloat16* __restrict__ out1, int S1, int SPAD1, int slot1)
{
    const float* x; int LDC, colofs, S, SPAD, slot; __nv_bfloat16* out;
    if (blockIdx.z == 0) { x = x0; LDC = LDC0; colofs = colofs0; out = out0; S = S0; SPAD = SPAD0; slot = slot0; }
    else                 { x = x1; LDC = LDC1; colofs = colofs1; out = out1; S = S1; SPAD = SPAD1; slot = slot1; }
    int bh = blockIdx.y, s0 = blockIdx.x * 32;
    if (s0 >= SPAD) return;
    int b = bh >> 4, h = bh & 15;
    float mn = g_stats[2 * slot], mx = g_stats[2 * slot + 1];
    float delta = (mx - mn) * (1.f / 255.f);
    float zp = rintf(-mn / delta);
    #pragma unroll
    for (int it = 0; it < 10; it++) {
        int local = threadIdx.x + it * 256;
        int sl = local / 80, d = local % 80;
        int s = s0 + sl;
        float val = 0.f;
        if (d < 72 && s < S) {
            float xv = x[((size_t)b * S + s) * LDC + colofs + h * HDIM + d];
            float q = fminf(fmaxf(rintf(xv / delta) + zp, 0.f), 255.f);
            val = q - zp;
        }
        out[((size_t)bh * SPAD + s) * 80 + d] = __float2bfloat16(val);
    }
}

// V: coalesced via 32x32 smem tile transpose.
__global__ __launch_bounds__(256) void quant_v_kernel(
    const float* __restrict__ x, int LDC, int colofs,
    __nv_bfloat16* __restrict__ out, int S, int SPAD, int slot)
{
    __shared__ float tile[32][33];
    int bh = blockIdx.y, s0 = blockIdx.x * 32;
    int b = bh >> 4, h = bh & 15;
    float mn = g_stats[2 * slot], mx = g_stats[2 * slot + 1];
    float delta = (mx - mn) * (1.f / 255.f);
    float zp = rintf(-mn / delta);
    int tx = threadIdx.x & 31, ty = threadIdx.x >> 5;

    for (int dc0 = 0; dc0 < 128; dc0 += 32) {
        #pragma unroll
        for (int r = ty; r < 32; r += 8) {
            int s = s0 + r, d = dc0 + tx;
            float val = 0.f;
            if (d < 72 && s < S) {
                float xv = x[((size_t)b * S + s) * LDC + colofs + h * HDIM + d];
                float q = fminf(fmaxf(rintf(xv / delta) + zp, 0.f), 255.f);
                val = q - zp;
            }
            tile[r][tx] = val;
        }
        __syncthreads();
        #pragma unroll
        for (int r = ty; r < 32; r += 8) {
            int d = dc0 + r;
            out[((size_t)bh * 128 + d) * SPAD + s0 + tx] = __float2bfloat16(tile[tx][r]);
        }
        __syncthreads();
    }
}

// ----------------------- pass 1: stats only (no score store) ----------------
__global__ __launch_bounds__(256) void stats_mma_kernel(int SK, int KROWS, float premul)
{
    __shared__ char sA[128 * 176];
    __shared__ char sB[128 * 176];
    int tid = threadIdx.x, wid = tid >> 5, lane = tid & 31;
    int bh = blockIdx.z;
    int kcol0 = blockIdx.x * 128, qrow0 = blockIdx.y * 128;
    int wm = wid & 3, wn = wid >> 2;
    uint32_t sa = smem_to_u32(sA), sb = smem_to_u32(sB);

    const __nv_bfloat16* qb = g_qi + ((size_t)bh * 1024 + qrow0) * 80;
    const __nv_bfloat16* kb = g_ki + ((size_t)bh * KROWS + kcol0) * 80;
    #pragma unroll
    for (int i = 0; i < 5; i++) {
        int c = tid + i * 256;
        int row = c / 10, j = c - row * 10;
        cp16(sa + row * 176 + j * 16, qb + (size_t)row * 80 + j * 8, 16u);
        cp16(sb + row * 176 + j * 16, kb + (size_t)row * 80 + j * 8, 16u);
    }
    asm volatile("cp.async.commit_group;" ::: "memory");
    cpasync_wait<0>();
    __syncthreads();

    float acc[2][8][4];
    #pragma unroll
    for (int mt = 0; mt < 2; mt++)
        #pragma unroll
        for (int nt = 0; nt < 8; nt++)
            #pragma unroll
            for (int e = 0; e < 4; e++) acc[mt][nt][e] = 0.f;

    #pragma unroll
    for (int kk = 0; kk < 5; kk++) {
        uint32_t af[2][4];
        #pragma unroll
        for (int mt = 0; mt < 2; mt++) {
            uint32_t arow = (uint32_t)(wm * 32 + mt * 16 + (lane & 15));
            ldsm_x4(af[mt], sa + arow * 176 + kk * 32 + ((lane >> 4) << 4));
        }
        #pragma unroll
        for (int bp = 0; bp < 4; bp++) {
            uint32_t brow = (uint32_t)(wn * 64 + bp * 16 + (lane & 7) + (((lane >> 4) & 1) << 3));
            uint32_t bf4[4];
            ldsm_x4(bf4, sb + brow * 176 + kk * 32 + (((lane >> 3) & 1) << 4));
            #pragma unroll
            for (int sub = 0; sub < 2; sub++) {
                int nt = bp * 2 + sub;
                #pragma unroll
                for (int mt = 0; mt < 2; mt++)
                    mma_bf16(acc[mt][nt], af[mt], bf4 + sub * 2);
            }
        }
    }

    float dq = (g_stats[1] - g_stats[0]) * (1.f / 255.f);
    float dk = (g_stats[3] - g_stats[2]) * (1.f / 255.f);
    float sc = dq * dk * premul;

    #pragma unroll
    for (int mt = 0; mt < 2; mt++) {
        #pragma unroll
        for (int h2 = 0; h2 < 2; h2++) {
            int r = qrow0 + wm * 32 + mt * 16 + (lane >> 2) + h2 * 8;
            float zs = 0.f, mxv = -INFINITY;
            #pragma unroll
            for (int nt = 0; nt < 8; nt++) {
                int c0 = kcol0 + wn * 64 + nt * 8 + (lane & 3) * 2;
                float v0 = acc[mt][nt][h2 * 2]     * sc;
                float v1 = acc[mt][nt][h2 * 2 + 1] * sc;
                if (c0 < SK)     { zs += fexp(v0); mxv = fmaxf(mxv, v0); }
                if (c0 + 1 < SK) { zs += fexp(v1); mxv = fmaxf(mxv, v1); }
            }
            #pragma unroll
            for (int o = 1; o <= 2; o <<= 1) {
                zs  += __shfl_xor_sync(0xffffffffu, zs, o);
                mxv = fmaxf(mxv, __shfl_xor_sync(0xffffffffu, mxv, o));
            }
            if ((lane & 3) == 0) {
                size_t prow = ((size_t)bh * SEQ + r) * 16 + blockIdx.x * 2 + wn;
                g_partZ[prow] = zs;
                g_partM[prow] = mxv;
            }
        }
    }
}

// ----------------------- row reduce: Z, pmax (deterministic) ----------------
__global__ __launch_bounds__(256) void rowreduce_kernel(int nparts) {
    int row = blockIdx.x * 256 + threadIdx.x;
    if (row >= NROWSBH) return;
    float Z = 0.f, M = -INFINITY;
    const float* pz = g_partZ + (size_t)row * 16;
    const float* pm = g_partM + (size_t)row * 16;
    for (int j = 0; j < nparts; j++) { Z += pz[j]; M = fmaxf(M, pm[j]); }
    g_rowZ[row] = Z;
    float pr = fexp(M) / Z;
    for (int o = 16; o; o >>= 1) pr = fmaxf(pr, __shfl_xor_sync(0xffffffffu, pr, o));
    __shared__ float sh[8];
    if ((threadIdx.x & 31) == 0) sh[threadIdx.x >> 5] = pr;
    __syncthreads();
    if (threadIdx.x == 0) {
        for (int i = 1; i < 8; i++) pr = fmaxf(pr, sh[i]);
        atomicMaxF(&g_stats[6], pr);
    }
}

// ----------------------- pass 2: fused flash-style attention ----------------
#define PV2_Q   0
#define PV2_K   22528
#define PV2_V   45056
#define PV2_P   81920
#define PV2_SC  100352
#define PV2_SMEM 100864

__global__ __launch_bounds__(256, 2) void pv2_kernel(
    __nv_bfloat16* __restrict__ oh, __nv_bfloat16* __restrict__ ol,
    int SK, int SKPAD, float premul)
{
    extern __shared__ char smem[];
    uint32_t sb = smem_to_u32(smem);
    float* sscale = (float*)(smem + PV2_SC);
    int tid = threadIdx.x, wid = tid >> 5, lane = tid & 31;
    int bh = blockIdx.y, m0 = blockIdx.x * 128;
    int b = bh >> 4, h = bh & 15;
    int wm = wid & 3, wn = wid >> 2;
    size_t rowbase = (size_t)bh * SEQ + m0;

    const __nv_bfloat16* qb = g_qi + ((size_t)bh * SEQ + m0) * 80;
    const __nv_bfloat16* kb = g_ki + (size_t)bh * SKPAD * 80;
    const __nv_bfloat16* vb = g_vi + (size_t)bh * 128 * SKPAD;
    const int KT = SKPAD >> 6;

    float pmax = g_stats[6];
    if (tid < 128)
        sscale[tid] = 255.f / (g_rowZ[rowbase + tid] * pmax);

    float dq = (g_stats[1] - g_stats[0]) * (1.f / 255.f);
    float dk = (g_stats[3] - g_stats[2]) * (1.f / 255.f);
    float sc = dq * dk * premul;

    #pragma unroll
    for (int i = 0; i < 5; i++) {
        int c = tid + i * 256;
        int row = c / 10, j = c - row * 10;
        cp16(sb + PV2_Q + row * 176 + j * 16, qb + (size_t)row * 80 + j * 8, 16u);
    }
    #pragma unroll
    for (int i = 0; i < 3; i++) {
        int c = tid + i * 256;
        if (c < 640) {
            int row = c / 10, j = c - row * 10;
            cp16(sb + PV2_K + row * 176 + j * 16, kb + (size_t)row * 80 + j * 8, 16u);
        }
    }
    #pragma unroll
    for (int i = 0; i < 4; i++) {
        int c = tid + i * 256;
        int row = c >> 3, j = c & 7;
        cp16(sb + PV2_V + row * 144 + j * 16, vb + (size_t)row * SKPAD + j * 8, 16u);
    }
    asm volatile("cp.async.commit_group;" ::: "memory");

    float acc_o[2][8][4];
    #pragma unroll
    for (int mt = 0; mt < 2; mt++)
        #pragma unroll
        for (int nt = 0; nt < 8; nt++)
            #pragma unroll
            for (int e = 0; e < 4; e++) acc_o[mt][nt][e] = 0.f;

    for (int t = 0; t < KT; t++) {
        if (t + 1 < KT) {
            uint32_t kbuf = sb + PV2_K + ((t + 1) & 1) * 11264;
            uint32_t vbuf = sb + PV2_V + ((t + 1) & 1) * 18432;
            const __nv_bfloat16* kg = kb + (size_t)(t + 1) * 64 * 80;
            const __nv_bfloat16* vg = vb + (size_t)(t + 1) * 64;
            #pragma unroll
            for (int i = 0; i < 3; i++) {
                int c = tid + i * 256;
                if (c < 640) {
                    int row = c / 10, j = c - row * 10;
                    cp16(kbuf + row * 176 + j * 16, kg + (size_t)row * 80 + j * 8, 16u);
                }
            }
            #pragma unroll
            for (int i = 0; i < 4; i++) {
                int c = tid + i * 256;
                int row = c >> 3, j = c & 7;
                cp16(vbuf + row * 144 + j * 16, vg + (size_t)row * SKPAD + j * 8, 16u);
            }
            asm volatile("cp.async.commit_group;" ::: "memory");
            cpasync_wait<1>();
        } else {
            cpasync_wait<0>();
        }
        __syncthreads();   // K/V(t) ready

        uint32_t kbase = sb + PV2_K + (t & 1) * 11264;
        uint32_t vbase = sb + PV2_V + (t & 1) * 18432;

        float acc_s[2][4][4];
        #pragma unroll
        for (int mt = 0; mt < 2; mt++)
            #pragma unroll
            for (int nt = 0; nt < 4; nt++)
                #pragma unroll
                for (int e = 0; e < 4; e++) acc_s[mt][nt][e] = 0.f;

        #pragma unroll
        for (int kk = 0; kk < 5; kk++) {
            uint32_t af[2][4];
            #pragma unroll
            for (int mt = 0; mt < 2; mt++) {
                uint32_t arow = (uint32_t)(wm * 32 + mt * 16 + (lane & 15));
                ldsm_x4(af[mt], sb + PV2_Q + arow * 176 + kk * 32 + ((lane >> 4) << 4));
            }
            #pragma unroll
            for (int bp = 0; bp < 2; bp++) {
                uint32_t brow = (uint32_t)(wn * 32 + bp * 16 + (lane & 7) + (((lane >> 4) & 1) << 3));
                uint32_t bf4[4];
                ldsm_x4(bf4, kbase + brow * 176 + kk * 32 + (((lane >> 3) & 1) << 4));
                #pragma unroll
                for (int sub = 0; sub < 2; sub++) {
                    int nt = bp * 2 + sub;
                    #pragma unroll
                    for (int mt = 0; mt < 2; mt++)
                        mma_bf16(acc_s[mt][nt], af[mt], bf4 + sub * 2);
                }
            }
        }

        #pragma unroll
        for (int mt = 0; mt < 2; mt++) {
            #pragma unroll
            for (int h2 = 0; h2 < 2; h2++) {
                int rl = wm * 32 + mt * 16 + (lane >> 2) + h2 * 8;
                float rsc = sscale[rl];
                #pragma unroll
                for (int nt = 0; nt < 4; nt++) {
                    int kcl = wn * 32 + nt * 8 + (lane & 3) * 2;
                    int kcg = t * 64 + kcl;
                    float p0 = 0.f, p1 = 0.f;
                    if (kcg < SK)
                        p0 = fminf(rintf(fexp(acc_s[mt][nt][h2 * 2] * sc) * rsc), 255.f);
                    if (kcg + 1 < SK)
                        p1 = fminf(rintf(fexp(acc_s[mt][nt][h2 * 2 + 1] * sc) * rsc), 255.f);
                    *(__nv_bfloat162*)(smem + PV2_P + rl * 144 + kcl * 2) =
                        __nv_bfloat162(__float2bfloat16(p0), __float2bfloat16(p1));
                }
            }
        }
        __syncthreads();   // P complete

        #pragma unroll
        for (int kk = 0; kk < 4; kk++) {
            uint32_t af[2][4];
            #pragma unroll
            for (int mt = 0; mt < 2; mt++) {
                uint32_t arow = (uint32_t)(wm * 32 + mt * 16 + (lane & 15));
                ldsm_x4(af[mt], sb + PV2_P + arow * 144 + kk * 32 + ((lane >> 4) << 4));
            }
            int bplim = (wn == 0) ? 4 : 1;
            for (int bp = 0; bp < bplim; bp++) {
                uint32_t brow = (uint32_t)(wn * 64 + bp * 16 + (lane & 7) + (((lane >> 4) & 1) << 3));
                uint32_t bf4[4];
                ldsm_x4(bf4, vbase + brow * 144 + kk * 32 + (((lane >> 3) & 1) << 4));
                #pragma unroll
                for (int sub = 0; sub < 2; sub++) {
                    int nt = bp * 2 + sub;
                    #pragma unroll
                    for (int mt = 0; mt < 2; mt++)
                        mma_bf16(acc_o[mt][nt], af[mt], bf4 + sub * 2);
                }
            }
        }
        __syncthreads();   // drain readers of K/V(t) before its buffer is reused
    }

    float dp = pmax * (1.f / 255.f);
    float dv = (g_stats[5] - g_stats[4]) * (1.f / 255.f);
    float osc = dp * dv;

    // output feeds Wo (fp16x2 GEMM) -> fp16 hi/lo split
    #pragma unroll
    for (int mt = 0; mt < 2; mt++) {
        int r0 = m0 + wm * 32 + mt * 16 + (lane >> 2);
        #pragma unroll
        for (int nt = 0; nt < 8; nt++) {
            int n = wn * 64 + nt * 8 + (lane & 3) * 2;
            if (n >= 72) continue;
            #pragma unroll
            for (int h2 = 0; h2 < 2; h2++) {
                int r = r0 + h2 * 8;
                size_t idx = ((size_t)b * SEQ + r) * DMODEL + h * HDIM + n;
                split_store_h(oh, ol, idx,     acc_o[mt][nt][h2 * 2]     * osc);
                split_store_h(oh, ol, idx + 1, acc_o[mt][nt][h2 * 2 + 1] * osc);
            }
        }
    }
}

// ----------------------- host orchestration ---------------------------------
static void tc_gemm(int mode,
                    const __nv_bfloat16* ah, const __nv_bfloat16* al,
                    const __nv_bfloat16* bh, const __nv_bfloat16* bl,
                    const float* bias, const float* res,
                    float* C, int M, int N, int K, int slot = -1,
                    __nv_bfloat16* ggh = nullptr, __nv_bfloat16* ggl = nullptr) {
    static bool attr_set = false;
    if (!attr_set) {
        cudaFuncSetAttribute(tc_gemm_kernel<0>, cudaFuncAttributeMaxDynamicSharedMemorySize,
                             TC_SMEM_TOTAL);
        cudaFuncSetAttribute(tc_gemm_kernel<1>, cudaFuncAttributeMaxDynamicSharedMemorySize,
                             TC_SMEM_TOTAL);
        cudaFuncSetAttribute(pv2_kernel, cudaFuncAttributeMaxDynamicSharedMemorySize,
                             PV2_SMEM);
        attr_set = true;
    }
    dim3 grid(N / 128, (M + 127) / 128);
    if (mode == 0)
        tc_gemm_kernel<0><<<grid, 256, TC_SMEM_TOTAL>>>(ah, al, bh, bl,
                                                        bias, res, C, M, N, K, slot, ggh, ggl);
    else
        tc_gemm_kernel<1><<<grid, 256, TC_SMEM_TOTAL>>>(ah, al, bh, bl,
                                                        bias, res, C, M, N, K, slot, ggh, ggl);
}

extern "C" void kernel_launch(void* const* d_in, const int* in_sizes, int n_in,
                              void* d_out, int out_size) {
    (void)in_sizes; (void)n_in; (void)out_size;
    const float* hs    = (const float*)d_in[0];
    const float* enc   = (const float*)d_in[1];
    const float* ln1g  = (const float*)d_in[2];
    const float* ln1b  = (const float*)d_in[3];
    const float* Wq1   = (const float*)d_in[4];
    const float* Wk1   = (const float*)d_in[5];
    const float* Wv1   = (const float*)d_in[6];
    const float* Wo1   = (const float*)d_in[7];
    const float* bo1   = (const float*)d_in[8];
    const float* ln2g  = (const float*)d_in[9];
    const float* ln2b  = (const float*)d_in[10];
    const float* Wq2   = (const float*)d_in[11];
    const float* Wk2   = (const float*)d_in[12];
    const float* Wv2   = (const float*)d_in[13];
    const float* Wo2   = (const float*)d_in[14];
    const float* bo2   = (const float*)d_in[15];
    const float* ln3g  = (const float*)d_in[16];
    const float* ln3b  = (const float*)d_in[17];
    const float* Wff1  = (const float*)d_in[18];
    const float* bff1  = (const float*)d_in[19];
    const float* Wff2  = (const float*)d_in[20];
    const float* bff2  = (const float*)d_in[21];
    float* out = (float*)d_out;

    void* p;
    cudaGetSymbolAddress(&p, g_q);      float* q_  = (float*)p;
    cudaGetSymbolAddress(&p, g_proj);   float* pj_ = (float*)p;
    __nv_bfloat16 *ah_, *al_, *gh_, *gl_, *bh_, *bl_;
    cudaGetSymbolAddress(&p, g_ah);   ah_ = (__nv_bfloat16*)p;
    cudaGetSymbolAddress(&p, g_al);   al_ = (__nv_bfloat16*)p;
    cudaGetSymbolAddress(&p, g_gh);   gh_ = (__nv_bfloat16*)p;
    cudaGetSymbolAddress(&p, g_gl);   gl_ = (__nv_bfloat16*)p;
    cudaGetSymbolAddress(&p, g_bh);   bh_ = (__nv_bfloat16*)p;
    cudaGetSymbolAddress(&p, g_bl);   bl_ = (__nv_bfloat16*)p;
    __nv_bfloat16 *qi_, *ki_, *vi_;
    cudaGetSymbolAddress(&p, g_qi);   qi_ = (__nv_bfloat16*)p;
    cudaGetSymbolAddress(&p, g_ki);   ki_ = (__nv_bfloat16*)p;
    cudaGetSymbolAddress(&p, g_vi);   vi_ = (__nv_bfloat16*)p;

    const float premul = 1.0f / sqrtf((float)HDIM);
    const size_t nE = (size_t)ENCROWS * DMODEL;
    const size_t WSTRIDE = (size_t)DMODEL * DMODEL;

    // ================= self-attention (fused QKV GEMM, bf16x3) ==============
    init_stats_kernel<<<1, 32>>>();
    ln_split_kernel<<<ROWS, 256>>>(hs, ln1g, ln1b, ah_, al_, 0);
    wt_trans_split_kernel<<<dim3(36, 36, 3), 256>>>(
        Wq1, Wk1, Wv1, DMODEL, DMODEL, 0, 0, 1, 0, bh_, bl_, WSTRIDE, 0);
    tc_gemm(0, ah_, al_, bh_, bl_, nullptr, nullptr, pj_, ROWS, 3456, DMODEL, 0);
    quant_qk2_kernel<<<dim3(32, BH, 2), 256>>>(
        pj_, 3456, 0,    qi_, SEQ, 1024, 0,
        pj_, 3456, 1152, ki_, SEQ, 1024, 1);
    quant_v_kernel<<<dim3(32, BH), 256>>>(pj_, 3456, 2304, vi_, SEQ, 1024, 2);
    stats_mma_kernel<<<dim3(8, 8, BH), 256>>>(SEQ, 1024, premul);
    rowreduce_kernel<<<NROWSBH / 256, 256>>>(16);
    pv2_kernel<<<dim3(8, BH), 256, PV2_SMEM>>>(ah_, al_, SEQ, 1024, premul);
    // Wo1: fp16x2
    wt_trans_split_kernel<<<dim3(36, 36, 1), 256>>>(
        Wo1, Wo1, Wo1, DMODEL, DMODEL, 0, 0, 1, 0, bh_, bl_, 0, 1);
    tc_gemm(1, ah_, al_, bh_, bl_, bo1, hs, out, ROWS, DMODEL, DMODEL);

    // ================= cross-attention (fused KV GEMM, bf16x3) ==============
    init_stats_kernel<<<1, 32>>>();
    ln_split_kernel<<<ROWS, 256>>>(out, ln2g, ln2b, ah_, al_, 0);
    wt_trans_split_kernel<<<dim3(36, 36, 1), 256>>>(
        Wq2, Wq2, Wq2, DMODEL, DMODEL, 0, 0, 1, 0, bh_, bl_, 0, 0);
    tc_gemm(0, ah_, al_, bh_, bl_, nullptr, nullptr, q_, ROWS, DMODEL, DMODEL, 0);
    convert_split_kernel<<<2048, 256>>>(enc, nE / 4, ah_, al_);
    wt_trans_split_kernel<<<dim3(36, 36, 2), 256>>>(
        Wk2, Wv2, Wv2, DMODEL, DMODEL, 0, 0, 1, 0, bh_, bl_, WSTRIDE, 0);
    tc_gemm(0, ah_, al_, bh_, bl_, nullptr, nullptr, pj_, ENCROWS, 2304, DMODEL, 1);
    quant_qk2_kernel<<<dim3(32, BH, 2), 256>>>(
        q_,  1152, 0, qi_, SEQ,  1024, 0,
        pj_, 2304, 0, ki_, SENC, 128,  1);
    quant_v_kernel<<<dim3(4, BH), 256>>>(pj_, 2304, 1152, vi_, SENC, 128, 2);
    stats_mma_kernel<<<dim3(1, 8, BH), 256>>>(SENC, 128, premul);
    rowreduce_kernel<<<NROWSBH / 256, 256>>>(2);
    pv2_kernel<<<dim3(8, BH), 256, PV2_SMEM>>>(ah_, al_, SENC, 128, premul);
    // Wo2: fp16x2
    wt_trans_split_kernel<<<dim3(36, 36, 1), 256>>>(
        Wo2, Wo2, Wo2, DMODEL, DMODEL, 0, 0, 1, 0, bh_, bl_, 0, 1);
    tc_gemm(1, ah_, al_, bh_, bl_, bo2, out, out, ROWS, DMODEL, DMODEL);

    // ================= feed-forward (fp16x2, GEGLU fused into FF1) ==========
    ln_split_kernel<<<ROWS, 256>>>(out, ln3g, ln3b, ah_, al_, 1);
    wt_trans_split_kernel<<<dim3(FFD / 32, DMODEL / 32, 2), 256>>>(
        Wff1, Wff1, Wff1, DMODEL, 2 * FFD, 0, FFD, 2, 1, bh_, bl_, 0, 1);
    tc_gemm(1, ah_, al_, bh_, bl_, bff1, nullptr, nullptr, ROWS, 2 * FFD, DMODEL, -1,
            gh_, gl_);
    wt_trans_split_kernel<<<dim3(36, FFD / 32, 1), 256>>>(
        Wff2, Wff2, Wff2, FFD, DMODEL, 0, 0, 1, 0, bh_, bl_, 0, 1);
    tc_gemm(1, gh_, gl_, bh_, bl_, bff2, out, out, ROWS, DMODEL, FFD);
}